// round 13
// baseline (speedup 1.0000x reference)
#include <cuda_runtime.h>
#include <cuda_bf16.h>
#include <cuda_fp16.h>
#include <math.h>
#include <stdint.h>

// Problem constants
#define BB   2
#define SS   2048
#define DD   1024
#define HH   16
#define DHH  64
#define DMM  4096
#define NTOK (BB*SS)          // 4096
#define EPSLN 1e-5f

typedef __nv_bfloat16  bf16;
typedef __nv_bfloat162 bf162;

// ---------------------------------------------------------------------------
// Device scratch (all 2-byte buffers shared between bf16/fp16 phases by cast)
// ---------------------------------------------------------------------------
__device__ float g_mid[NTOK*DD];
__device__ float g_bias[3*DD];        // concatenated QKV bias
__device__ bf16  g_xh [NTOK*DD];      // split activations hi
__device__ bf16  g_xl [NTOK*DD];      // split activations lo
__device__ bf16  g_qkvh[NTOK*3*DD];   // fused QKV output (hi, fp16)
__device__ bf16  g_qkvl[NTOK*3*DD];   // fused QKV output (lo, fp16)
__device__ bf16  g_acth[NTOK*DMM];    // gelu output split (hi, fp16)
__device__ bf16  g_actl[NTOK*DMM];    // gelu output split (lo, fp16)
__device__ bf16  g_wh [DD*DMM];       // split/single transposed weight (hi)
__device__ bf16  g_wl [DD*DMM];       // split transposed weight (lo)

// ---------------------------------------------------------------------------
// Helpers
// ---------------------------------------------------------------------------
__device__ __forceinline__ void split2h(float x, __half& h, __half& l)
{
    h = __float2half_rn(x);
    l = __float2half_rn(x - __half2float(h));
}

__device__ __forceinline__ uint32_t cvta_s(const void* p)
{
    return (uint32_t)__cvta_generic_to_shared(p);
}

__device__ __forceinline__ void cp16(uint32_t s, const void* g)
{
    asm volatile("cp.async.cg.shared.global [%0], [%1], 16;" :: "r"(s), "l"(g));
}

__device__ __forceinline__ void ldsm4(unsigned r[4], uint32_t a)
{
    asm volatile("ldmatrix.sync.aligned.m8n8.x4.shared.b16 {%0,%1,%2,%3}, [%4];"
                 : "=r"(r[0]), "=r"(r[1]), "=r"(r[2]), "=r"(r[3]) : "r"(a));
}

__device__ __forceinline__ void ldsm4t(unsigned r[4], uint32_t a)
{
    asm volatile("ldmatrix.sync.aligned.m8n8.x4.trans.shared.b16 {%0,%1,%2,%3}, [%4];"
                 : "=r"(r[0]), "=r"(r[1]), "=r"(r[2]), "=r"(r[3]) : "r"(a));
}

// fp16 inputs, fp32 accumulator (half-rate path)
__device__ __forceinline__ void mma16816h(float c[4], const unsigned a[4],
                                          const unsigned b[2])
{
    asm volatile(
        "mma.sync.aligned.m16n8k16.row.col.f32.f16.f16.f32 "
        "{%0,%1,%2,%3}, {%4,%5,%6,%7}, {%8,%9}, {%0,%1,%2,%3};"
        : "+f"(c[0]), "+f"(c[1]), "+f"(c[2]), "+f"(c[3])
        : "r"(a[0]), "r"(a[1]), "r"(a[2]), "r"(a[3]), "r"(b[0]), "r"(b[1]));
}

// fp16 inputs, fp16 accumulator (hypothesis: full-rate path)
__device__ __forceinline__ void mma16816hh(unsigned c[2], const unsigned a[4],
                                           const unsigned b[2])
{
    asm volatile(
        "mma.sync.aligned.m16n8k16.row.col.f16.f16.f16.f16 "
        "{%0,%1}, {%2,%3,%4,%5}, {%6,%7}, {%0,%1};"
        : "+r"(c[0]), "+r"(c[1])
        : "r"(a[0]), "r"(a[1]), "r"(a[2]), "r"(a[3]), "r"(b[0]), "r"(b[1]));
}

// unpack f16 accumulator pair into fp32 accumulator
__device__ __forceinline__ void addhacc(float c[4], const unsigned h[2])
{
    float2 f0 = __half22float2(*(const __half2*)&h[0]);
    float2 f1 = __half22float2(*(const __half2*)&h[1]);
    c[0] += f0.x; c[1] += f0.y; c[2] += f1.x; c[3] += f1.y;
}

__device__ __forceinline__ float gelu_exact(float x)
{
    return 0.5f * x * (1.0f + erff(x * 0.70710678118654752f));
}

// ---------------------------------------------------------------------------
// LayerNorm + split to fp16 hi/lo. One block per row, 256 threads.
// ---------------------------------------------------------------------------
__global__ __launch_bounds__(256)
void ln_split_kernel(const float* __restrict__ x, const float* __restrict__ w,
                     const float* __restrict__ b, __half* __restrict__ oh,
                     __half* __restrict__ ol)
{
    __shared__ float red[8];
    __shared__ float bcast;
    const int row = blockIdx.x;
    const int tid = threadIdx.x;
    const int lane = tid & 31, warp = tid >> 5;

    float4 v = ((const float4*)(x + (size_t)row * DD))[tid];

    float s = v.x + v.y + v.z + v.w;
    #pragma unroll
    for (int o = 16; o > 0; o >>= 1) s += __shfl_xor_sync(0xffffffffu, s, o);
    if (lane == 0) red[warp] = s;
    __syncthreads();
    if (tid < 8) {
        float t = red[tid];
        #pragma unroll
        for (int o = 4; o > 0; o >>= 1) t += __shfl_xor_sync(0xffu, t, o);
        if (tid == 0) bcast = t;
    }
    __syncthreads();
    const float mean = bcast * (1.0f / DD);
    __syncthreads();

    float dx0 = v.x - mean, dx1 = v.y - mean, dx2 = v.z - mean, dx3 = v.w - mean;
    float sq = dx0*dx0 + dx1*dx1 + dx2*dx2 + dx3*dx3;
    #pragma unroll
    for (int o = 16; o > 0; o >>= 1) sq += __shfl_xor_sync(0xffffffffu, sq, o);
    if (lane == 0) red[warp] = sq;
    __syncthreads();
    if (tid < 8) {
        float t = red[tid];
        #pragma unroll
        for (int o = 4; o > 0; o >>= 1) t += __shfl_xor_sync(0xffu, t, o);
        if (tid == 0) bcast = t;
    }
    __syncthreads();
    const float inv = rsqrtf(bcast * (1.0f / DD) + EPSLN);

    float4 wv = ((const float4*)w)[tid];
    float4 bv = ((const float4*)b)[tid];
    float o0 = dx0 * inv * wv.x + bv.x;
    float o1 = dx1 * inv * wv.y + bv.y;
    float o2 = dx2 * inv * wv.z + bv.z;
    float o3 = dx3 * inv * wv.w + bv.w;

    __half h0,h1,h2,h3,l0,l1,l2,l3;
    split2h(o0,h0,l0); split2h(o1,h1,l1); split2h(o2,h2,l2); split2h(o3,h3,l3);
    __half2* H = (__half2*)(oh + (size_t)row * DD + tid * 4);
    __half2* L = (__half2*)(ol + (size_t)row * DD + tid * 4);
    H[0] = __halves2half2(h0, h1); H[1] = __halves2half2(h2, h3);
    L[0] = __halves2half2(l0, l1); L[1] = __halves2half2(l2, l3);
}

// ---------------------------------------------------------------------------
// Concatenate QKV biases into g_bias[3072]
// ---------------------------------------------------------------------------
__global__ void concat_bias(const float* __restrict__ bq,
                            const float* __restrict__ bk,
                            const float* __restrict__ bv,
                            float* __restrict__ out)
{
    int i = blockIdx.x * blockDim.x + threadIdx.x;
    float v;
    if (i < DD) v = bq[i];
    else if (i < 2*DD) v = bk[i - DD];
    else v = bv[i - 2*DD];
    out[i] = v;
}

// ---------------------------------------------------------------------------
// Transpose + single-fp16 convert: out16[(c)*R + r] = fp16(in[r][c])
// ---------------------------------------------------------------------------
__global__ __launch_bounds__(256)
void tsplit16_kernel(const float* __restrict__ in, __half* __restrict__ o16,
                     int R, int C)
{
    __shared__ float t[32][33];
    const int tx = threadIdx.x, ty = threadIdx.y;
    const int c0 = blockIdx.x * 32, r0 = blockIdx.y * 32;
    #pragma unroll
    for (int i = 0; i < 4; i++)
        t[ty + 8*i][tx] = in[(size_t)(r0 + ty + 8*i) * C + c0 + tx];
    __syncthreads();
    #pragma unroll
    for (int i = 0; i < 4; i++) {
        int c = c0 + ty + 8*i;
        o16[(size_t)c * R + r0 + tx] = __float2half_rn(t[tx][ty + 8*i]);
    }
}

// ---------------------------------------------------------------------------
// Transpose + fp16 hi/lo split for QKV weights
// ---------------------------------------------------------------------------
__global__ __launch_bounds__(256)
void tsplit_qkv(const float* __restrict__ wq, const float* __restrict__ wk,
                const float* __restrict__ wv, __half* __restrict__ oh,
                __half* __restrict__ ol)
{
    __shared__ float t[32][33];
    const int tx = threadIdx.x, ty = threadIdx.y;
    const int c0 = blockIdx.x * 32, r0 = blockIdx.y * 32;
    const int z = blockIdx.z;
    const int which = z >> 4, h = z & 15;
    const float* src = (which == 0 ? wq : (which == 1 ? wk : wv))
                       + (size_t)h * DD * DHH;
    #pragma unroll
    for (int i = 0; i < 4; i++)
        t[ty + 8*i][tx] = src[(size_t)(r0 + ty + 8*i) * DHH + c0 + tx];
    __syncthreads();
    #pragma unroll
    for (int i = 0; i < 4; i++) {
        int c = c0 + ty + 8*i;
        float v = t[tx][ty + 8*i];
        size_t n = (size_t)which * DD + h * DHH + c;
        size_t off = n * DD + r0 + tx;
        __half hh, ll; split2h(v, hh, ll);
        oh[off] = hh; ol[off] = ll;
    }
}

// ---------------------------------------------------------------------------
// 3-term split-fp16 HMMA GEMM (QKV): C = Ah*Bh (f32acc) + [Al*Bh + Ah*Bl]
// (corrections chained in a transient f16 accumulator -> unpack-add).
// EPI fixed: bias + Q-scale -> split fp16.
// ---------------------------------------------------------------------------
#define TILE_BYTES 8192            // 128 rows * 64B
#define STG_BYTES  (4*TILE_BYTES)
#define GEMM_SMEM  (3*STG_BYTES)   // 98304 B

__global__ __launch_bounds__(256, 2)
void gemm_f16_qkv(const __half* __restrict__ Ah, const __half* __restrict__ Al,
                  const __half* __restrict__ Bh, const __half* __restrict__ Bl,
                  const float* __restrict__ bias,
                  __half* __restrict__ Oh, __half* __restrict__ Ol,
                  int M, int N, int K)
{
    extern __shared__ bf16 sm[];
    const int tid = threadIdx.x;
    const int bx = blockIdx.x, by = blockIdx.y;
    const int warp = tid >> 5, lane = tid & 31;
    const int wm = warp >> 1, wn = warp & 1;

    const int lrow = tid >> 1;
    const int lhalf = (tid & 1);
    const __half* gAh = Ah + (size_t)(by * 128 + lrow) * K + lhalf * 16;
    const __half* gAl = Al + (size_t)(by * 128 + lrow) * K + lhalf * 16;
    const __half* gBh = Bh + (size_t)(bx * 128 + lrow) * K + lhalf * 16;
    const __half* gBl = Bl + (size_t)(bx * 128 + lrow) * K + lhalf * 16;
    const uint32_t sbase = cvta_s(sm);
    const uint32_t lxm = (uint32_t)((lrow & 6) << 3);
    const uint32_t lso0 = lrow * 64 + ((lhalf * 32)      ^ lxm);
    const uint32_t lso1 = lrow * 64 + ((lhalf * 32 + 16) ^ lxm);

    float acc[2][8][4];
    #pragma unroll
    for (int i = 0; i < 2; i++)
        #pragma unroll
        for (int j = 0; j < 8; j++)
            #pragma unroll
            for (int q = 0; q < 4; q++) acc[i][j][q] = 0.0f;

    const int a_r = (lane & 7) + ((lane >> 3) & 1) * 8;
    const int a_c = (lane >> 4) * 8;
    const int b_r = (lane & 7) + (lane >> 4) * 8;
    const int b_c = ((lane >> 3) & 1) * 8;

    uint32_t arow[2], axm[2];
    #pragma unroll
    for (int mf = 0; mf < 2; mf++) {
        int r = wm*32 + mf*16 + a_r;
        arow[mf] = (uint32_t)r * 64;
        axm[mf]  = (uint32_t)((r & 6) << 3);
    }
    uint32_t brow[4], bxm[4];
    #pragma unroll
    for (int p = 0; p < 4; p++) {
        int r = wn*64 + p*16 + b_r;
        brow[p] = (uint32_t)r * 64;
        bxm[p]  = (uint32_t)((r & 6) << 3);
    }
    const uint32_t acb = (uint32_t)(a_c * 2);
    const uint32_t bcb = (uint32_t)(b_c * 2);

    const int T = K / 32;

    auto issue = [&](int s, int kk) {
        uint32_t st = sbase + (uint32_t)s * STG_BYTES;
        cp16(st + lso0,                gAh + kk);
        cp16(st + lso1,                gAh + kk + 8);
        cp16(st + TILE_BYTES   + lso0, gAl + kk);
        cp16(st + TILE_BYTES   + lso1, gAl + kk + 8);
        cp16(st + TILE_BYTES*2 + lso0, gBh + kk);
        cp16(st + TILE_BYTES*2 + lso1, gBh + kk + 8);
        cp16(st + TILE_BYTES*3 + lso0, gBl + kk);
        cp16(st + TILE_BYTES*3 + lso1, gBl + kk + 8);
        asm volatile("cp.async.commit_group;");
    };

    issue(0, 0);
    if (T > 1) issue(1, 32);

    int stage = 0;
    for (int t = 0; t < T; t++) {
        if (t + 2 < T) {
            issue((stage + 2) % 3, (t + 2) * 32);
            asm volatile("cp.async.wait_group 2;");
        } else if (t + 1 < T) {
            asm volatile("cp.async.wait_group 1;");
        } else {
            asm volatile("cp.async.wait_group 0;");
        }
        __syncthreads();

        const uint32_t st  = sbase + (uint32_t)stage * STG_BYTES;
        const uint32_t sAh = st;
        const uint32_t sAl = st + TILE_BYTES;
        const uint32_t sBh = st + TILE_BYTES*2;
        const uint32_t sBl = st + TILE_BYTES*3;

        #pragma unroll
        for (int kc = 0; kc < 2; kc++) {
            const uint32_t kb = (uint32_t)(kc * 32);
            unsigned ah[2][4], al[2][4];
            #pragma unroll
            for (int mf = 0; mf < 2; mf++) {
                uint32_t ao = arow[mf] + ((kb + acb) ^ axm[mf]);
                ldsm4(ah[mf], sAh + ao);
                ldsm4(al[mf], sAl + ao);
            }
            #pragma unroll
            for (int p = 0; p < 4; p++) {
                unsigned bh4[4], bl4[4];
                uint32_t bo = brow[p] + ((kb + bcb) ^ bxm[p]);
                ldsm4(bh4, sBh + bo);
                ldsm4(bl4, sBl + bo);
                #pragma unroll
                for (int mf = 0; mf < 2; mf++) {
                    // hi term (f32 acc)
                    mma16816h(acc[mf][2*p],     ah[mf], bh4);
                    mma16816h(acc[mf][2*p + 1], ah[mf], bh4 + 2);
                    // corrections chained in f16 acc
                    unsigned c0[2] = {0u, 0u}, c1[2] = {0u, 0u};
                    mma16816hh(c0, al[mf], bh4);
                    mma16816hh(c0, ah[mf], bl4);
                    mma16816hh(c1, al[mf], bh4 + 2);
                    mma16816hh(c1, ah[mf], bl4 + 2);
                    addhacc(acc[mf][2*p],     c0);
                    addhacc(acc[mf][2*p + 1], c1);
                }
            }
        }
        __syncthreads();
        stage = (stage + 1) % 3;
    }

    const int er = by * 128 + wm * 32 + (lane >> 2);
    const int ec = bx * 128 + wn * 64 + (lane & 3) * 2;
    #pragma unroll
    for (int mf = 0; mf < 2; mf++) {
        #pragma unroll
        for (int nf = 0; nf < 8; nf++) {
            int c = ec + nf * 8;
            float b0 = bias[c], b1 = bias[c + 1];
            float sc = (c < DD) ? 0.125f : 1.0f;
            #pragma unroll
            for (int half = 0; half < 2; half++) {
                int r = er + mf * 16 + half * 8;
                float v0 = (acc[mf][nf][half * 2 + 0] + b0) * sc;
                float v1 = (acc[mf][nf][half * 2 + 1] + b1) * sc;
                __half h0,h1,l0,l1;
                split2h(v0,h0,l0); split2h(v1,h1,l1);
                *(__half2*)(Oh + (size_t)r * N + c) = __halves2half2(h0, h1);
                *(__half2*)(Ol + (size_t)r * N + c) = __halves2half2(l0, l1);
            }
        }
    }
}

// ---------------------------------------------------------------------------
// 2-term split-fp16 HMMA GEMM: C = Ah@B (f32acc) + Al@B (f16acc transient)
// EPI: 1 = bias+gelu -> fp16 hi/lo    2 = bias+residual -> fp32
// ---------------------------------------------------------------------------
#define EPI_GELU16 1
#define EPI_RES32  2

#define STG2_BYTES (3*TILE_BYTES)   // Ah, Al, B = 24KB
#define GEMM2_SMEM (3*STG2_BYTES)   // 73728 B

template <int EPI>
__global__ __launch_bounds__(256, 2)
void gemm_f16(const __half* __restrict__ Ah, const __half* __restrict__ Al,
              const __half* __restrict__ Bm,
              const float* __restrict__ bias, const float* __restrict__ Rm,
              float* __restrict__ Cf, __half* __restrict__ Oh,
              __half* __restrict__ Ol, int M, int N, int K)
{
    extern __shared__ bf16 sm[];
    const int tid = threadIdx.x;
    const int bx = blockIdx.x, by = blockIdx.y;
    const int warp = tid >> 5, lane = tid & 31;
    const int wm = warp >> 1, wn = warp & 1;

    const int lrow = tid >> 1;
    const int lhalf = (tid & 1);
    const __half* gAh = Ah + (size_t)(by * 128 + lrow) * K + lhalf * 16;
    const __half* gAl = Al + (size_t)(by * 128 + lrow) * K + lhalf * 16;
    const __half* gB  = Bm + (size_t)(bx * 128 + lrow) * K + lhalf * 16;
    const uint32_t sbase = cvta_s(sm);
    const uint32_t lxm = (uint32_t)((lrow & 6) << 3);
    const uint32_t lso0 = lrow * 64 + ((lhalf * 32)      ^ lxm);
    const uint32_t lso1 = lrow * 64 + ((lhalf * 32 + 16) ^ lxm);

    float acc[2][8][4];
    #pragma unroll
    for (int i = 0; i < 2; i++)
        #pragma unroll
        for (int j = 0; j < 8; j++)
            #pragma unroll
            for (int q = 0; q < 4; q++) acc[i][j][q] = 0.0f;

    const int a_r = (lane & 7) + ((lane >> 3) & 1) * 8;
    const int a_c = (lane >> 4) * 8;
    const int b_r = (lane & 7) + (lane >> 4) * 8;
    const int b_c = ((lane >> 3) & 1) * 8;

    uint32_t arow[2], axm[2];
    #pragma unroll
    for (int mf = 0; mf < 2; mf++) {
        int r = wm*32 + mf*16 + a_r;
        arow[mf] = (uint32_t)r * 64;
        axm[mf]  = (uint32_t)((r & 6) << 3);
    }
    uint32_t brow[4], bxm[4];
    #pragma unroll
    for (int p = 0; p < 4; p++) {
        int r = wn*64 + p*16 + b_r;
        brow[p] = (uint32_t)r * 64;
        bxm[p]  = (uint32_t)((r & 6) << 3);
    }
    const uint32_t acb = (uint32_t)(a_c * 2);
    const uint32_t bcb = (uint32_t)(b_c * 2);

    const int T = K / 32;

    auto issue = [&](int s, int kk) {
        uint32_t st = sbase + (uint32_t)s * STG2_BYTES;
        cp16(st + lso0,                gAh + kk);
        cp16(st + lso1,                gAh + kk + 8);
        cp16(st + TILE_BYTES   + lso0, gAl + kk);
        cp16(st + TILE_BYTES   + lso1, gAl + kk + 8);
        cp16(st + TILE_BYTES*2 + lso0, gB  + kk);
        cp16(st + TILE_BYTES*2 + lso1, gB  + kk + 8);
        asm volatile("cp.async.commit_group;");
    };

    issue(0, 0);
    if (T > 1) issue(1, 32);

    int stage = 0;
    for (int t = 0; t < T; t++) {
        if (t + 2 < T) {
            issue((stage + 2) % 3, (t + 2) * 32);
            asm volatile("cp.async.wait_group 2;");
        } else if (t + 1 < T) {
            asm volatile("cp.async.wait_group 1;");
        } else {
            asm volatile("cp.async.wait_group 0;");
        }
        __syncthreads();

        const uint32_t st  = sbase + (uint32_t)stage * STG2_BYTES;
        const uint32_t sAh = st;
        const uint32_t sAl = st + TILE_BYTES;
        const uint32_t sB  = st + TILE_BYTES*2;

        #pragma unroll
        for (int kc = 0; kc < 2; kc++) {
            const uint32_t kb = (uint32_t)(kc * 32);
            unsigned ah[2][4], al[2][4];
            #pragma unroll
            for (int mf = 0; mf < 2; mf++) {
                uint32_t ao = arow[mf] + ((kb + acb) ^ axm[mf]);
                ldsm4(ah[mf], sAh + ao);
                ldsm4(al[mf], sAl + ao);
            }
            #pragma unroll
            for (int p = 0; p < 4; p++) {
                unsigned b4[4];
                uint32_t bo = brow[p] + ((kb + bcb) ^ bxm[p]);
                ldsm4(b4, sB + bo);
                #pragma unroll
                for (int mf = 0; mf < 2; mf++) {
                    // hi term (f32 acc)
                    mma16816h(acc[mf][2*p],     ah[mf], b4);
                    mma16816h(acc[mf][2*p + 1], ah[mf], b4 + 2);
                    // lo term (f16 acc transient)
                    unsigned c0[2] = {0u, 0u}, c1[2] = {0u, 0u};
                    mma16816hh(c0, al[mf], b4);
                    mma16816hh(c1, al[mf], b4 + 2);
                    addhacc(acc[mf][2*p],     c0);
                    addhacc(acc[mf][2*p + 1], c1);
                }
            }
        }
        __syncthreads();
        stage = (stage + 1) % 3;
    }

    const int er = by * 128 + wm * 32 + (lane >> 2);
    const int ec = bx * 128 + wn * 64 + (lane & 3) * 2;
    #pragma unroll
    for (int mf = 0; mf < 2; mf++) {
        #pragma unroll
        for (int nf = 0; nf < 8; nf++) {
            int c = ec + nf * 8;
            float b0 = bias[c], b1 = bias[c + 1];
            #pragma unroll
            for (int half = 0; half < 2; half++) {
                int r = er + mf * 16 + half * 8;
                float v0 = acc[mf][nf][half * 2 + 0] + b0;
                float v1 = acc[mf][nf][half * 2 + 1] + b1;
                if (EPI == EPI_GELU16) {
                    v0 = gelu_exact(v0); v1 = gelu_exact(v1);
                    __half h0,h1,l0,l1;
                    split2h(v0,h0,l0); split2h(v1,h1,l1);
                    *(__half2*)(Oh + (size_t)r * N + c) = __halves2half2(h0, h1);
                    *(__half2*)(Ol + (size_t)r * N + c) = __halves2half2(l0, l1);
                } else {
                    float2 rr = *(const float2*)(Rm + (size_t)r * N + c);
                    v0 += rr.x; v1 += rr.y;
                    float2 o; o.x = v0; o.y = v1;
                    *(float2*)(Cf + (size_t)r * N + c) = o;
                }
            }
        }
    }
}

// ---------------------------------------------------------------------------
// Tensor-core flash attention, fp16 split inputs, fp16 split z output.
// Structure identical to the passing bf16 version (dtype swap only).
// ---------------------------------------------------------------------------
#define AQS   72
#define ATILE (64*AQS)
#define ATTN_SMEM ((2*ATILE + 8*ATILE) * 2)

__global__ __launch_bounds__(128, 2)
void attn_mma(const __half* __restrict__ qkvh, const __half* __restrict__ qkvl,
              __half* __restrict__ zh, __half* __restrict__ zl)
{
    extern __shared__ bf16 smb[];
    const uint32_t sbase = cvta_s(smb);
    const int tid  = threadIdx.x;
    const int warp = tid >> 5, lane = tid & 31;
    const int qt = blockIdx.x;
    const int bh = blockIdx.y;
    const int h  = bh & 15;
    const int hcol = h * DHH;
    const int tokbase = (bh >> 4) * SS;

    const uint32_t oQh = 0, oQl = ATILE;
    auto stageoff = [](int s) { return (uint32_t)(2*ATILE + s*4*ATILE); };

    const int ldrow = tid >> 1;
    const int ldc0  = (tid & 1) * 32;
    auto ld_tensor = [&](uint32_t selems, const __half* g, int tok0, int coff) {
        const __half* gp = g + (size_t)(tok0 + ldrow) * (3*DD) + coff + ldc0;
        uint32_t sp = sbase + (selems + ldrow * AQS + ldc0) * 2;
        cp16(sp,      gp);
        cp16(sp + 16, gp + 8);
        cp16(sp + 32, gp + 16);
        cp16(sp + 48, gp + 24);
    };
    auto issue_kv = [&](int s, int kt) {
        int tok0 = tokbase + kt * 64;
        uint32_t so = stageoff(s);
        ld_tensor(so,           qkvh, tok0, DD   + hcol);
        ld_tensor(so + ATILE,   qkvl, tok0, DD   + hcol);
        ld_tensor(so + 2*ATILE, qkvh, tok0, 2*DD + hcol);
        ld_tensor(so + 3*ATILE, qkvl, tok0, 2*DD + hcol);
        asm volatile("cp.async.commit_group;");
    };

    {
        int tok0 = tokbase + qt * 64;
        ld_tensor(oQh, qkvh, tok0, hcol);
        ld_tensor(oQl, qkvl, tok0, hcol);
        issue_kv(0, 0);
    }

    const int a_r  = (lane & 7) + ((lane >> 3) & 1) * 8;
    const int a_c  = (lane >> 4) * 8;
    const int kb_r = (lane & 7) + (lane >> 4) * 8;
    const int kb_c = ((lane >> 3) & 1) * 8;
    const int vb_r = (lane & 7) + ((lane >> 3) & 1) * 8;
    const int vb_c = (lane >> 4) * 8;

    unsigned qh[4][4], ql[4][4];
    float o[8][4];
    #pragma unroll
    for (int j = 0; j < 8; j++)
        #pragma unroll
        for (int q = 0; q < 4; q++) o[j][q] = 0.0f;
    float m0 = -INFINITY, m1 = -INFINITY, l0 = 0.0f, l1 = 0.0f;

    const int r0 = lane >> 2;
    const int colq = 2 * (lane & 3);

    for (int kt = 0; kt <= qt; kt++) {
        if (kt + 1 <= qt) {
            issue_kv((kt + 1) & 1, kt + 1);
            asm volatile("cp.async.wait_group 1;");
        } else {
            asm volatile("cp.async.wait_group 0;");
        }
        __syncthreads();

        if (kt == 0) {
            #pragma unroll
            for (int kc = 0; kc < 4; kc++) {
                uint32_t ao = ((warp*16 + a_r) * AQS + kc*16 + a_c) * 2;
                ldsm4(qh[kc], sbase + (oQh)*2 + ao);
                ldsm4(ql[kc], sbase + (oQl)*2 + ao);
            }
        }

        const uint32_t so = stageoff(kt & 1);
        const uint32_t sKh = sbase + so * 2;
        const uint32_t sKl = sbase + (so + ATILE) * 2;
        const uint32_t sVh = sbase + (so + 2*ATILE) * 2;
        const uint32_t sVl = sbase + (so + 3*ATILE) * 2;

        float s[8][4];
        #pragma unroll
        for (int j = 0; j < 8; j++)
            #pragma unroll
            for (int q = 0; q < 4; q++) s[j][q] = 0.0f;

        #pragma unroll
        for (int jp = 0; jp < 4; jp++) {
            #pragma unroll
            for (int kc = 0; kc < 4; kc++) {
                unsigned kh4[4], kl4[4];
                uint32_t ko = ((jp*16 + kb_r) * AQS + kc*16 + kb_c) * 2;
                ldsm4(kh4, sKh + ko);
                ldsm4(kl4, sKl + ko);
                mma16816h(s[2*jp],   qh[kc], kh4);
                mma16816h(s[2*jp+1], qh[kc], kh4 + 2);
                mma16816h(s[2*jp],   ql[kc], kh4);
                mma16816h(s[2*jp+1], ql[kc], kh4 + 2);
                mma16816h(s[2*jp],   qh[kc], kl4);
                mma16816h(s[2*jp+1], qh[kc], kl4 + 2);
            }
        }

        if (kt == qt) {
            const int rg0 = warp*16 + r0;
            #pragma unroll
            for (int j = 0; j < 8; j++) {
                int cg = j*8 + colq;
                if (cg     > rg0) s[j][0] = -1e30f;
                if (cg + 1 > rg0) s[j][1] = -1e30f;
                if (cg     > rg0 + 8) s[j][2] = -1e30f;
                if (cg + 1 > rg0 + 8) s[j][3] = -1e30f;
            }
        }

        float vmax0 = -INFINITY, vmax1 = -INFINITY;
        #pragma unroll
        for (int j = 0; j < 8; j++) {
            vmax0 = fmaxf(vmax0, fmaxf(s[j][0], s[j][1]));
            vmax1 = fmaxf(vmax1, fmaxf(s[j][2], s[j][3]));
        }
        vmax0 = fmaxf(vmax0, __shfl_xor_sync(0xffffffffu, vmax0, 1));
        vmax0 = fmaxf(vmax0, __shfl_xor_sync(0xffffffffu, vmax0, 2));
        vmax1 = fmaxf(vmax1, __shfl_xor_sync(0xffffffffu, vmax1, 1));
        vmax1 = fmaxf(vmax1, __shfl_xor_sync(0xffffffffu, vmax1, 2));

        float mn0 = fmaxf(m0, vmax0), mn1 = fmaxf(m1, vmax1);
        float f0 = __expf(m0 - mn0), f1 = __expf(m1 - mn1);
        m0 = mn0; m1 = mn1;

        float rs0 = 0.0f, rs1 = 0.0f;
        #pragma unroll
        for (int j = 0; j < 8; j++) {
            s[j][0] = __expf(s[j][0] - mn0);
            s[j][1] = __expf(s[j][1] - mn0);
            s[j][2] = __expf(s[j][2] - mn1);
            s[j][3] = __expf(s[j][3] - mn1);
            rs0 += s[j][0] + s[j][1];
            rs1 += s[j][2] + s[j][3];
        }
        rs0 += __shfl_xor_sync(0xffffffffu, rs0, 1);
        rs0 += __shfl_xor_sync(0xffffffffu, rs0, 2);
        rs1 += __shfl_xor_sync(0xffffffffu, rs1, 1);
        rs1 += __shfl_xor_sync(0xffffffffu, rs1, 2);
        l0 = l0 * f0 + rs0;
        l1 = l1 * f1 + rs1;

        #pragma unroll
        for (int j = 0; j < 8; j++) {
            o[j][0] *= f0; o[j][1] *= f0;
            o[j][2] *= f1; o[j][3] *= f1;
        }

        unsigned ph[4][4], pl[4][4];
        #pragma unroll
        for (int jc = 0; jc < 4; jc++) {
            const int j0 = 2*jc, j1 = 2*jc + 1;
            #define SPLITPAIR(a, b, HI, LOI)                          \
                {  __half _h0,_l0,_h1,_l1;                            \
                   split2h(a,_h0,_l0); split2h(b,_h1,_l1);            \
                   __half2 _th = __halves2half2(_h0,_h1);             \
                   __half2 _tl = __halves2half2(_l0,_l1);             \
                   HI  = *reinterpret_cast<unsigned*>(&_th);          \
                   LOI = *reinterpret_cast<unsigned*>(&_tl); }
            SPLITPAIR(s[j0][0], s[j0][1], ph[jc][0], pl[jc][0]);
            SPLITPAIR(s[j0][2], s[j0][3], ph[jc][1], pl[jc][1]);
            SPLITPAIR(s[j1][0], s[j1][1], ph[jc][2], pl[jc][2]);
            SPLITPAIR(s[j1][2], s[j1][3], ph[jc][3], pl[jc][3]);
            #undef SPLITPAIR
        }

        #pragma unroll
        for (int jc = 0; jc < 4; jc++) {
            #pragma unroll
            for (int np = 0; np < 4; np++) {
                unsigned vh4[4], vl4[4];
                uint32_t vo = ((jc*16 + vb_r) * AQS + np*16 + vb_c) * 2;
                ldsm4t(vh4, sVh + vo);
                ldsm4t(vl4, sVl + vo);
                mma16816h(o[2*np],   ph[jc], vh4);
                mma16816h(o[2*np+1], ph[jc], vh4 + 2);
                mma16816h(o[2*np],   pl[jc], vh4);
                mma16816h(o[2*np+1], pl[jc], vh4 + 2);
                mma16816h(o[2*np],   ph[jc], vl4);
                mma16816h(o[2*np+1], ph[jc], vl4 + 2);
            }
        }
        __syncthreads();
    }

    const float il0 = 1.0f / l0, il1 = 1.0f / l1;
    const int row0 = tokbase + qt*64 + warp*16 + r0;
    #pragma unroll
    for (int j = 0; j < 8; j++) {
        int c = hcol + j*8 + colq;
        float a0 = o[j][0] * il0, a1 = o[j][1] * il0;
        float b0 = o[j][2] * il1, b1 = o[j][3] * il1;
        __half h0,lo0,h1,lo1;
        split2h(a0,h0,lo0); split2h(a1,h1,lo1);
        *(__half2*)(zh + (size_t)row0 * DD + c) = __halves2half2(h0, h1);
        *(__half2*)(zl + (size_t)row0 * DD + c) = __halves2half2(lo0, lo1);
        split2h(b0,h0,lo0); split2h(b1,h1,lo1);
        *(__half2*)(zh + (size_t)(row0 + 8) * DD + c) = __halves2half2(h0, h1);
        *(__half2*)(zl + (size_t)(row0 + 8) * DD + c) = __halves2half2(lo0, lo1);
    }
}

// ---------------------------------------------------------------------------
// Host launcher
// ---------------------------------------------------------------------------
extern "C" void kernel_launch(void* const* d_in, const int* in_sizes, int n_in,
                              void* d_out, int out_size)
{
    (void)in_sizes; (void)n_in; (void)out_size;
    const float* resid = (const float*)d_in[0];
    const float* ln1w  = (const float*)d_in[1];
    const float* ln1b  = (const float*)d_in[2];
    const float* WQ    = (const float*)d_in[3];
    const float* bQ    = (const float*)d_in[4];
    const float* WK    = (const float*)d_in[5];
    const float* bK    = (const float*)d_in[6];
    const float* WV    = (const float*)d_in[7];
    const float* bV    = (const float*)d_in[8];
    const float* WO    = (const float*)d_in[9];
    const float* bO    = (const float*)d_in[10];
    const float* ln2w  = (const float*)d_in[11];
    const float* ln2b  = (const float*)d_in[12];
    const float* Win   = (const float*)d_in[13];
    const float* bin   = (const float*)d_in[14];
    const float* Wout  = (const float*)d_in[15];
    const float* bout  = (const float*)d_in[16];

    float *mid, *biasqkv;
    bf16 *xh, *xl, *qkvh_, *qkvl_, *acth, *actl, *wh, *wl;
    cudaGetSymbolAddress((void**)&mid,   g_mid);
    cudaGetSymbolAddress((void**)&biasqkv, g_bias);
    cudaGetSymbolAddress((void**)&xh,    g_xh);
    cudaGetSymbolAddress((void**)&xl,    g_xl);
    cudaGetSymbolAddress((void**)&qkvh_, g_qkvh);
    cudaGetSymbolAddress((void**)&qkvl_, g_qkvl);
    cudaGetSymbolAddress((void**)&acth,  g_acth);
    cudaGetSymbolAddress((void**)&actl,  g_actl);
    cudaGetSymbolAddress((void**)&wh,    g_wh);
    cudaGetSymbolAddress((void**)&wl,    g_wl);

    // fp16 aliases (same 2-byte storage)
    __half* x16h  = (__half*)xh;
    __half* x16l  = (__half*)xl;
    __half* qkv16h = (__half*)qkvh_;
    __half* qkv16l = (__half*)qkvl_;
    __half* a16h  = (__half*)acth;
    __half* a16l  = (__half*)actl;
    __half* w16h  = (__half*)wh;
    __half* w16l  = (__half*)wl;

    cudaFuncSetAttribute(attn_mma, cudaFuncAttributeMaxDynamicSharedMemorySize,
                         ATTN_SMEM);
    cudaFuncSetAttribute(gemm_f16_qkv,
                         cudaFuncAttributeMaxDynamicSharedMemorySize, GEMM_SMEM);
    cudaFuncSetAttribute(gemm_f16<EPI_GELU16>,
                         cudaFuncAttributeMaxDynamicSharedMemorySize, GEMM2_SMEM);
    cudaFuncSetAttribute(gemm_f16<EPI_RES32>,
                         cudaFuncAttributeMaxDynamicSharedMemorySize, GEMM2_SMEM);

    dim3 tb(32, 8);

    // 1) LN1 -> fp16 split
    ln_split_kernel<<<NTOK, 256>>>(resid, ln1w, ln1b, x16h, x16l);

    // 2) fused QKV (fp16 3-term, f16-acc corrections; Q prescaled by 1/8)
    concat_bias<<<12, 256>>>(bQ, bK, bV, biasqkv);
    tsplit_qkv<<<dim3(DHH/32, DD/32, 48), tb>>>(WQ, WK, WV, w16h, w16l);
    gemm_f16_qkv<<<dim3(3*DD/128, NTOK/128), 256, GEMM_SMEM>>>(
        x16h, x16l, w16h, w16l, biasqkv, qkv16h, qkv16l, NTOK, 3*DD, DD);

    // 3) attention (fp16) -> z fp16 split (into x16h/x16l)
    dim3 ga(SS / 64, BB * HH);
    attn_mma<<<ga, 128, ATTN_SMEM>>>(qkv16h, qkv16l, x16h, x16l);

    // 4) O-projection + residual -> mid (2-term fp16, f16-acc lo)
    tsplit16_kernel<<<dim3(DD/32, DD/32), tb>>>(WO, w16h, DD, DD);
    gemm_f16<EPI_RES32><<<dim3(DD/128, NTOK/128), 256, GEMM2_SMEM>>>(
        x16h, x16l, w16h, bO, resid, mid, nullptr, nullptr, NTOK, DD, DD);

    // 5) LN2 -> fp16 split
    ln_split_kernel<<<NTOK, 256>>>(mid, ln2w, ln2b, x16h, x16l);

    // 6) MLP in + exact GELU -> fp16 split act (2-term fp16, f16-acc lo)
    tsplit16_kernel<<<dim3(DMM/32, DD/32), tb>>>(Win, w16h, DD, DMM);
    gemm_f16<EPI_GELU16><<<dim3(DMM/128, NTOK/128), 256, GEMM2_SMEM>>>(
        x16h, x16l, w16h, bin, nullptr, nullptr, a16h, a16l, NTOK, DMM, DD);

    // 7) MLP out + bias + residual -> d_out (2-term fp16, f16-acc lo)
    tsplit16_kernel<<<dim3(DD/32, DMM/32), tb>>>(Wout, w16h, DMM, DD);
    gemm_f16<EPI_RES32><<<dim3(DD/128, NTOK/128), 256, GEMM2_SMEM>>>(
        a16h, a16l, w16h, bout, mid, (float*)d_out, nullptr, nullptr,
        NTOK, DD, DMM);
}

// round 14
// speedup vs baseline: 1.3932x; 1.3932x over previous
#include <cuda_runtime.h>
#include <cuda_bf16.h>
#include <cuda_fp16.h>
#include <math.h>
#include <stdint.h>

// Problem constants
#define BB   2
#define SS   2048
#define DD   1024
#define HH   16
#define DHH  64
#define DMM  4096
#define NTOK (BB*SS)          // 4096
#define EPSLN 1e-5f

typedef __nv_bfloat16  bf16;

// ---------------------------------------------------------------------------
// Device scratch (2-byte buffers, fp16 phase)
// ---------------------------------------------------------------------------
__device__ float g_mid[NTOK*DD];
__device__ float g_bias[3*DD];        // concatenated QKV bias
__device__ bf16  g_xh [NTOK*DD];      // split activations hi (fp16)
__device__ bf16  g_xl [NTOK*DD];      // split activations lo (fp16)
__device__ bf16  g_qkvh[NTOK*3*DD];   // fused QKV output (hi, fp16)
__device__ bf16  g_qkvl[NTOK*3*DD];   // fused QKV output (lo, fp16)
__device__ bf16  g_acth[NTOK*DMM];    // gelu output split (hi, fp16)
__device__ bf16  g_actl[NTOK*DMM];    // gelu output split (lo, fp16)
__device__ bf16  g_wh [DD*DMM];       // single transposed weight (fp16)

// ---------------------------------------------------------------------------
// Helpers
// ---------------------------------------------------------------------------
__device__ __forceinline__ void split2h(float x, __half& h, __half& l)
{
    h = __float2half_rn(x);
    l = __float2half_rn(x - __half2float(h));
}

__device__ __forceinline__ uint32_t cvta_s(const void* p)
{
    return (uint32_t)__cvta_generic_to_shared(p);
}

__device__ __forceinline__ void cp16(uint32_t s, const void* g)
{
    asm volatile("cp.async.cg.shared.global [%0], [%1], 16;" :: "r"(s), "l"(g));
}

__device__ __forceinline__ void ldsm4(unsigned r[4], uint32_t a)
{
    asm volatile("ldmatrix.sync.aligned.m8n8.x4.shared.b16 {%0,%1,%2,%3}, [%4];"
                 : "=r"(r[0]), "=r"(r[1]), "=r"(r[2]), "=r"(r[3]) : "r"(a));
}

__device__ __forceinline__ void ldsm4t(unsigned r[4], uint32_t a)
{
    asm volatile("ldmatrix.sync.aligned.m8n8.x4.trans.shared.b16 {%0,%1,%2,%3}, [%4];"
                 : "=r"(r[0]), "=r"(r[1]), "=r"(r[2]), "=r"(r[3]) : "r"(a));
}

// fp16 inputs, fp32 accumulator
__device__ __forceinline__ void mma16816h(float c[4], const unsigned a[4],
                                          const unsigned b[2])
{
    asm volatile(
        "mma.sync.aligned.m16n8k16.row.col.f32.f16.f16.f32 "
        "{%0,%1,%2,%3}, {%4,%5,%6,%7}, {%8,%9}, {%0,%1,%2,%3};"
        : "+f"(c[0]), "+f"(c[1]), "+f"(c[2]), "+f"(c[3])
        : "r"(a[0]), "r"(a[1]), "r"(a[2]), "r"(a[3]), "r"(b[0]), "r"(b[1]));
}

__device__ __forceinline__ float gelu_exact(float x)
{
    return 0.5f * x * (1.0f + erff(x * 0.70710678118654752f));
}

// ---------------------------------------------------------------------------
// LayerNorm + split to fp16 hi/lo. One block per row, 256 threads.
// ---------------------------------------------------------------------------
__global__ __launch_bounds__(256)
void ln_split_kernel(const float* __restrict__ x, const float* __restrict__ w,
                     const float* __restrict__ b, __half* __restrict__ oh,
                     __half* __restrict__ ol)
{
    __shared__ float red[8];
    __shared__ float bcast;
    const int row = blockIdx.x;
    const int tid = threadIdx.x;
    const int lane = tid & 31, warp = tid >> 5;

    float4 v = ((const float4*)(x + (size_t)row * DD))[tid];

    float s = v.x + v.y + v.z + v.w;
    #pragma unroll
    for (int o = 16; o > 0; o >>= 1) s += __shfl_xor_sync(0xffffffffu, s, o);
    if (lane == 0) red[warp] = s;
    __syncthreads();
    if (tid < 8) {
        float t = red[tid];
        #pragma unroll
        for (int o = 4; o > 0; o >>= 1) t += __shfl_xor_sync(0xffu, t, o);
        if (tid == 0) bcast = t;
    }
    __syncthreads();
    const float mean = bcast * (1.0f / DD);
    __syncthreads();

    float dx0 = v.x - mean, dx1 = v.y - mean, dx2 = v.z - mean, dx3 = v.w - mean;
    float sq = dx0*dx0 + dx1*dx1 + dx2*dx2 + dx3*dx3;
    #pragma unroll
    for (int o = 16; o > 0; o >>= 1) sq += __shfl_xor_sync(0xffffffffu, sq, o);
    if (lane == 0) red[warp] = sq;
    __syncthreads();
    if (tid < 8) {
        float t = red[tid];
        #pragma unroll
        for (int o = 4; o > 0; o >>= 1) t += __shfl_xor_sync(0xffu, t, o);
        if (tid == 0) bcast = t;
    }
    __syncthreads();
    const float inv = rsqrtf(bcast * (1.0f / DD) + EPSLN);

    float4 wv = ((const float4*)w)[tid];
    float4 bv = ((const float4*)b)[tid];
    float o0 = dx0 * inv * wv.x + bv.x;
    float o1 = dx1 * inv * wv.y + bv.y;
    float o2 = dx2 * inv * wv.z + bv.z;
    float o3 = dx3 * inv * wv.w + bv.w;

    __half h0,h1,h2,h3,l0,l1,l2,l3;
    split2h(o0,h0,l0); split2h(o1,h1,l1); split2h(o2,h2,l2); split2h(o3,h3,l3);
    __half2* H = (__half2*)(oh + (size_t)row * DD + tid * 4);
    __half2* L = (__half2*)(ol + (size_t)row * DD + tid * 4);
    H[0] = __halves2half2(h0, h1); H[1] = __halves2half2(h2, h3);
    L[0] = __halves2half2(l0, l1); L[1] = __halves2half2(l2, l3);
}

// ---------------------------------------------------------------------------
// Concatenate QKV biases into g_bias[3072]
// ---------------------------------------------------------------------------
__global__ void concat_bias(const float* __restrict__ bq,
                            const float* __restrict__ bk,
                            const float* __restrict__ bv,
                            float* __restrict__ out)
{
    int i = blockIdx.x * blockDim.x + threadIdx.x;
    float v;
    if (i < DD) v = bq[i];
    else if (i < 2*DD) v = bk[i - DD];
    else v = bv[i - 2*DD];
    out[i] = v;
}

// ---------------------------------------------------------------------------
// Transpose + single-fp16 convert: o16[c*R + r] = fp16(in[r][c])
// ---------------------------------------------------------------------------
__global__ __launch_bounds__(256)
void tsplit16_kernel(const float* __restrict__ in, __half* __restrict__ o16,
                     int R, int C)
{
    __shared__ float t[32][33];
    const int tx = threadIdx.x, ty = threadIdx.y;
    const int c0 = blockIdx.x * 32, r0 = blockIdx.y * 32;
    #pragma unroll
    for (int i = 0; i < 4; i++)
        t[ty + 8*i][tx] = in[(size_t)(r0 + ty + 8*i) * C + c0 + tx];
    __syncthreads();
    #pragma unroll
    for (int i = 0; i < 4; i++) {
        int c = c0 + ty + 8*i;
        o16[(size_t)c * R + r0 + tx] = __float2half_rn(t[tx][ty + 8*i]);
    }
}

// ---------------------------------------------------------------------------
// Transpose + single-fp16 for QKV weights: z -> (which = z/16, head = z%16)
// writes row n = which*1024 + head*64 + c of B[N=3072][K=1024]
// ---------------------------------------------------------------------------
__global__ __launch_bounds__(256)
void tsplit16_qkv(const float* __restrict__ wq, const float* __restrict__ wk,
                  const float* __restrict__ wv, __half* __restrict__ o16)
{
    __shared__ float t[32][33];
    const int tx = threadIdx.x, ty = threadIdx.y;
    const int c0 = blockIdx.x * 32, r0 = blockIdx.y * 32;
    const int z = blockIdx.z;
    const int which = z >> 4, h = z & 15;
    const float* src = (which == 0 ? wq : (which == 1 ? wk : wv))
                       + (size_t)h * DD * DHH;
    #pragma unroll
    for (int i = 0; i < 4; i++)
        t[ty + 8*i][tx] = src[(size_t)(r0 + ty + 8*i) * DHH + c0 + tx];
    __syncthreads();
    #pragma unroll
    for (int i = 0; i < 4; i++) {
        int c = c0 + ty + 8*i;
        size_t n = (size_t)which * DD + h * DHH + c;
        o16[n * DD + r0 + tx] = __float2half_rn(t[tx][ty + 8*i]);
    }
}

// ---------------------------------------------------------------------------
// 2-term split-fp16 HMMA GEMM: C = (Ah + Al) @ B16, all f32-acc MMAs.
// A fp16 hi/lo [M][K]; B single fp16 [N][K].
// 3-stage cp.async, packed 64B rows + SW64 swizzle.
// EPI: 1 = bias+gelu -> fp16 hi/lo   2 = bias+residual -> fp32
//      3 = QKV: bias + Q-scale -> fp16 hi/lo
// ---------------------------------------------------------------------------
#define EPI_GELU16 1
#define EPI_RES32  2
#define EPI_QKV16  3

#define TILE_BYTES 8192             // 128 rows * 64B
#define STG2_BYTES (3*TILE_BYTES)   // Ah, Al, B = 24KB
#define GEMM2_SMEM (3*STG2_BYTES)   // 73728 B

template <int EPI>
__global__ __launch_bounds__(256, 2)
void gemm_f16(const __half* __restrict__ Ah, const __half* __restrict__ Al,
              const __half* __restrict__ Bm,
              const float* __restrict__ bias, const float* __restrict__ Rm,
              float* __restrict__ Cf, __half* __restrict__ Oh,
              __half* __restrict__ Ol, int M, int N, int K)
{
    extern __shared__ bf16 sm[];
    const int tid = threadIdx.x;
    const int bx = blockIdx.x, by = blockIdx.y;
    const int warp = tid >> 5, lane = tid & 31;
    const int wm = warp >> 1, wn = warp & 1;

    const int lrow = tid >> 1;
    const int lhalf = (tid & 1);
    const __half* gAh = Ah + (size_t)(by * 128 + lrow) * K + lhalf * 16;
    const __half* gAl = Al + (size_t)(by * 128 + lrow) * K + lhalf * 16;
    const __half* gB  = Bm + (size_t)(bx * 128 + lrow) * K + lhalf * 16;
    const uint32_t sbase = cvta_s(sm);
    const uint32_t lxm = (uint32_t)((lrow & 6) << 3);
    const uint32_t lso0 = lrow * 64 + ((lhalf * 32)      ^ lxm);
    const uint32_t lso1 = lrow * 64 + ((lhalf * 32 + 16) ^ lxm);

    float acc[2][8][4];
    #pragma unroll
    for (int i = 0; i < 2; i++)
        #pragma unroll
        for (int j = 0; j < 8; j++)
            #pragma unroll
            for (int q = 0; q < 4; q++) acc[i][j][q] = 0.0f;

    const int a_r = (lane & 7) + ((lane >> 3) & 1) * 8;
    const int a_c = (lane >> 4) * 8;
    const int b_r = (lane & 7) + (lane >> 4) * 8;
    const int b_c = ((lane >> 3) & 1) * 8;

    uint32_t arow[2], axm[2];
    #pragma unroll
    for (int mf = 0; mf < 2; mf++) {
        int r = wm*32 + mf*16 + a_r;
        arow[mf] = (uint32_t)r * 64;
        axm[mf]  = (uint32_t)((r & 6) << 3);
    }
    uint32_t brow[4], bxm[4];
    #pragma unroll
    for (int p = 0; p < 4; p++) {
        int r = wn*64 + p*16 + b_r;
        brow[p] = (uint32_t)r * 64;
        bxm[p]  = (uint32_t)((r & 6) << 3);
    }
    const uint32_t acb = (uint32_t)(a_c * 2);
    const uint32_t bcb = (uint32_t)(b_c * 2);

    const int T = K / 32;

    auto issue = [&](int s, int kk) {
        uint32_t st = sbase + (uint32_t)s * STG2_BYTES;
        cp16(st + lso0,                gAh + kk);
        cp16(st + lso1,                gAh + kk + 8);
        cp16(st + TILE_BYTES   + lso0, gAl + kk);
        cp16(st + TILE_BYTES   + lso1, gAl + kk + 8);
        cp16(st + TILE_BYTES*2 + lso0, gB  + kk);
        cp16(st + TILE_BYTES*2 + lso1, gB  + kk + 8);
        asm volatile("cp.async.commit_group;");
    };

    issue(0, 0);
    if (T > 1) issue(1, 32);

    int stage = 0;
    for (int t = 0; t < T; t++) {
        if (t + 2 < T) {
            issue((stage + 2) % 3, (t + 2) * 32);
            asm volatile("cp.async.wait_group 2;");
        } else if (t + 1 < T) {
            asm volatile("cp.async.wait_group 1;");
        } else {
            asm volatile("cp.async.wait_group 0;");
        }
        __syncthreads();

        const uint32_t st  = sbase + (uint32_t)stage * STG2_BYTES;
        const uint32_t sAh = st;
        const uint32_t sAl = st + TILE_BYTES;
        const uint32_t sB  = st + TILE_BYTES*2;

        #pragma unroll
        for (int kc = 0; kc < 2; kc++) {
            const uint32_t kb = (uint32_t)(kc * 32);
            unsigned ah[2][4], al[2][4];
            #pragma unroll
            for (int mf = 0; mf < 2; mf++) {
                uint32_t ao = arow[mf] + ((kb + acb) ^ axm[mf]);
                ldsm4(ah[mf], sAh + ao);
                ldsm4(al[mf], sAl + ao);
            }
            #pragma unroll
            for (int p = 0; p < 4; p++) {
                unsigned b4[4];
                uint32_t bo = brow[p] + ((kb + bcb) ^ bxm[p]);
                ldsm4(b4, sB + bo);
                #pragma unroll
                for (int mf = 0; mf < 2; mf++) {
                    mma16816h(acc[mf][2*p],     ah[mf], b4);
                    mma16816h(acc[mf][2*p + 1], ah[mf], b4 + 2);
                    mma16816h(acc[mf][2*p],     al[mf], b4);
                    mma16816h(acc[mf][2*p + 1], al[mf], b4 + 2);
                }
            }
        }
        __syncthreads();
        stage = (stage + 1) % 3;
    }

    const int er = by * 128 + wm * 32 + (lane >> 2);
    const int ec = bx * 128 + wn * 64 + (lane & 3) * 2;
    #pragma unroll
    for (int mf = 0; mf < 2; mf++) {
        #pragma unroll
        for (int nf = 0; nf < 8; nf++) {
            int c = ec + nf * 8;
            float b0 = bias[c], b1 = bias[c + 1];
            #pragma unroll
            for (int half = 0; half < 2; half++) {
                int r = er + mf * 16 + half * 8;
                float v0 = acc[mf][nf][half * 2 + 0] + b0;
                float v1 = acc[mf][nf][half * 2 + 1] + b1;
                if (EPI == EPI_GELU16 || EPI == EPI_QKV16) {
                    if (EPI == EPI_GELU16) {
                        v0 = gelu_exact(v0); v1 = gelu_exact(v1);
                    } else {
                        float sc = (c < DD) ? 0.125f : 1.0f;
                        v0 *= sc; v1 *= sc;
                    }
                    __half h0,h1,l0,l1;
                    split2h(v0,h0,l0); split2h(v1,h1,l1);
                    *(__half2*)(Oh + (size_t)r * N + c) = __halves2half2(h0, h1);
                    *(__half2*)(Ol + (size_t)r * N + c) = __halves2half2(l0, l1);
                } else {
                    float2 rr = *(const float2*)(Rm + (size_t)r * N + c);
                    v0 += rr.x; v1 += rr.y;
                    float2 o; o.x = v0; o.y = v1;
                    *(float2*)(Cf + (size_t)r * N + c) = o;
                }
            }
        }
    }
}

// ---------------------------------------------------------------------------
// Tensor-core flash attention, fp16, 2-term both phases:
//   S = (Qh + Ql) @ Kh^T       O = (Ph + Pl) @ Vh
// KV stages hold only hi tensors (half the smem / cp.async of 3-term).
// ---------------------------------------------------------------------------
#define AQS   72
#define ATILE (64*AQS)
#define ATTN_SMEM ((2*ATILE + 2*2*ATILE) * 2)   // Qh,Ql + 2 stages * {Kh,Vh}

__global__ __launch_bounds__(128, 2)
void attn_mma(const __half* __restrict__ qkvh, const __half* __restrict__ qkvl,
              __half* __restrict__ zh, __half* __restrict__ zl)
{
    extern __shared__ bf16 smb[];
    const uint32_t sbase = cvta_s(smb);
    const int tid  = threadIdx.x;
    const int warp = tid >> 5, lane = tid & 31;
    const int qt = blockIdx.x;
    const int bh = blockIdx.y;
    const int h  = bh & 15;
    const int hcol = h * DHH;
    const int tokbase = (bh >> 4) * SS;

    const uint32_t oQh = 0, oQl = ATILE;
    auto stageoff = [](int s) { return (uint32_t)(2*ATILE + s*2*ATILE); };

    const int ldrow = tid >> 1;
    const int ldc0  = (tid & 1) * 32;
    auto ld_tensor = [&](uint32_t selems, const __half* g, int tok0, int coff) {
        const __half* gp = g + (size_t)(tok0 + ldrow) * (3*DD) + coff + ldc0;
        uint32_t sp = sbase + (selems + ldrow * AQS + ldc0) * 2;
        cp16(sp,      gp);
        cp16(sp + 16, gp + 8);
        cp16(sp + 32, gp + 16);
        cp16(sp + 48, gp + 24);
    };
    auto issue_kv = [&](int s, int kt) {
        int tok0 = tokbase + kt * 64;
        uint32_t so = stageoff(s);
        ld_tensor(so,           qkvh, tok0, DD   + hcol);   // Kh
        ld_tensor(so + ATILE,   qkvh, tok0, 2*DD + hcol);   // Vh
        asm volatile("cp.async.commit_group;");
    };

    {
        int tok0 = tokbase + qt * 64;
        ld_tensor(oQh, qkvh, tok0, hcol);
        ld_tensor(oQl, qkvl, tok0, hcol);
        issue_kv(0, 0);
    }

    const int a_r  = (lane & 7) + ((lane >> 3) & 1) * 8;
    const int a_c  = (lane >> 4) * 8;
    const int kb_r = (lane & 7) + (lane >> 4) * 8;
    const int kb_c = ((lane >> 3) & 1) * 8;
    const int vb_r = (lane & 7) + ((lane >> 3) & 1) * 8;
    const int vb_c = (lane >> 4) * 8;

    unsigned qh[4][4], ql[4][4];
    float o[8][4];
    #pragma unroll
    for (int j = 0; j < 8; j++)
        #pragma unroll
        for (int q = 0; q < 4; q++) o[j][q] = 0.0f;
    float m0 = -INFINITY, m1 = -INFINITY, l0 = 0.0f, l1 = 0.0f;

    const int r0 = lane >> 2;
    const int colq = 2 * (lane & 3);

    for (int kt = 0; kt <= qt; kt++) {
        if (kt + 1 <= qt) {
            issue_kv((kt + 1) & 1, kt + 1);
            asm volatile("cp.async.wait_group 1;");
        } else {
            asm volatile("cp.async.wait_group 0;");
        }
        __syncthreads();

        if (kt == 0) {
            #pragma unroll
            for (int kc = 0; kc < 4; kc++) {
                uint32_t ao = ((warp*16 + a_r) * AQS + kc*16 + a_c) * 2;
                ldsm4(qh[kc], sbase + (oQh)*2 + ao);
                ldsm4(ql[kc], sbase + (oQl)*2 + ao);
            }
        }

        const uint32_t so = stageoff(kt & 1);
        const uint32_t sKh = sbase + so * 2;
        const uint32_t sVh = sbase + (so + ATILE) * 2;

        // ---- S = (Qh + Ql) @ Kh^T ----
        float s[8][4];
        #pragma unroll
        for (int j = 0; j < 8; j++)
            #pragma unroll
            for (int q = 0; q < 4; q++) s[j][q] = 0.0f;

        #pragma unroll
        for (int jp = 0; jp < 4; jp++) {
            #pragma unroll
            for (int kc = 0; kc < 4; kc++) {
                unsigned kh4[4];
                uint32_t ko = ((jp*16 + kb_r) * AQS + kc*16 + kb_c) * 2;
                ldsm4(kh4, sKh + ko);
                mma16816h(s[2*jp],   qh[kc], kh4);
                mma16816h(s[2*jp+1], qh[kc], kh4 + 2);
                mma16816h(s[2*jp],   ql[kc], kh4);
                mma16816h(s[2*jp+1], ql[kc], kh4 + 2);
            }
        }

        if (kt == qt) {
            const int rg0 = warp*16 + r0;
            #pragma unroll
            for (int j = 0; j < 8; j++) {
                int cg = j*8 + colq;
                if (cg     > rg0) s[j][0] = -1e30f;
                if (cg + 1 > rg0) s[j][1] = -1e30f;
                if (cg     > rg0 + 8) s[j][2] = -1e30f;
                if (cg + 1 > rg0 + 8) s[j][3] = -1e30f;
            }
        }

        float vmax0 = -INFINITY, vmax1 = -INFINITY;
        #pragma unroll
        for (int j = 0; j < 8; j++) {
            vmax0 = fmaxf(vmax0, fmaxf(s[j][0], s[j][1]));
            vmax1 = fmaxf(vmax1, fmaxf(s[j][2], s[j][3]));
        }
        vmax0 = fmaxf(vmax0, __shfl_xor_sync(0xffffffffu, vmax0, 1));
        vmax0 = fmaxf(vmax0, __shfl_xor_sync(0xffffffffu, vmax0, 2));
        vmax1 = fmaxf(vmax1, __shfl_xor_sync(0xffffffffu, vmax1, 1));
        vmax1 = fmaxf(vmax1, __shfl_xor_sync(0xffffffffu, vmax1, 2));

        float mn0 = fmaxf(m0, vmax0), mn1 = fmaxf(m1, vmax1);
        float f0 = __expf(m0 - mn0), f1 = __expf(m1 - mn1);
        m0 = mn0; m1 = mn1;

        float rs0 = 0.0f, rs1 = 0.0f;
        #pragma unroll
        for (int j = 0; j < 8; j++) {
            s[j][0] = __expf(s[j][0] - mn0);
            s[j][1] = __expf(s[j][1] - mn0);
            s[j][2] = __expf(s[j][2] - mn1);
            s[j][3] = __expf(s[j][3] - mn1);
            rs0 += s[j][0] + s[j][1];
            rs1 += s[j][2] + s[j][3];
        }
        rs0 += __shfl_xor_sync(0xffffffffu, rs0, 1);
        rs0 += __shfl_xor_sync(0xffffffffu, rs0, 2);
        rs1 += __shfl_xor_sync(0xffffffffu, rs1, 1);
        rs1 += __shfl_xor_sync(0xffffffffu, rs1, 2);
        l0 = l0 * f0 + rs0;
        l1 = l1 * f1 + rs1;

        #pragma unroll
        for (int j = 0; j < 8; j++) {
            o[j][0] *= f0; o[j][1] *= f0;
            o[j][2] *= f1; o[j][3] *= f1;
        }

        // ---- repack P into fp16 hi/lo A fragments ----
        unsigned ph[4][4], pl[4][4];
        #pragma unroll
        for (int jc = 0; jc < 4; jc++) {
            const int j0 = 2*jc, j1 = 2*jc + 1;
            #define SPLITPAIR(a, b, HI, LOI)                          \
                {  __half _h0,_l0,_h1,_l1;                            \
                   split2h(a,_h0,_l0); split2h(b,_h1,_l1);            \
                   __half2 _th = __halves2half2(_h0,_h1);             \
                   __half2 _tl = __halves2half2(_l0,_l1);             \
                   HI  = *reinterpret_cast<unsigned*>(&_th);          \
                   LOI = *reinterpret_cast<unsigned*>(&_tl); }
            SPLITPAIR(s[j0][0], s[j0][1], ph[jc][0], pl[jc][0]);
            SPLITPAIR(s[j0][2], s[j0][3], ph[jc][1], pl[jc][1]);
            SPLITPAIR(s[j1][0], s[j1][1], ph[jc][2], pl[jc][2]);
            SPLITPAIR(s[j1][2], s[j1][3], ph[jc][3], pl[jc][3]);
            #undef SPLITPAIR
        }

        // ---- O += (Ph + Pl) @ Vh ----
        #pragma unroll
        for (int jc = 0; jc < 4; jc++) {
            #pragma unroll
            for (int np = 0; np < 4; np++) {
                unsigned vh4[4];
                uint32_t vo = ((jc*16 + vb_r) * AQS + np*16 + vb_c) * 2;
                ldsm4t(vh4, sVh + vo);
                mma16816h(o[2*np],   ph[jc], vh4);
                mma16816h(o[2*np+1], ph[jc], vh4 + 2);
                mma16816h(o[2*np],   pl[jc], vh4);
                mma16816h(o[2*np+1], pl[jc], vh4 + 2);
            }
        }
        __syncthreads();
    }

    const float il0 = 1.0f / l0, il1 = 1.0f / l1;
    const int row0 = tokbase + qt*64 + warp*16 + r0;
    #pragma unroll
    for (int j = 0; j < 8; j++) {
        int c = hcol + j*8 + colq;
        float a0 = o[j][0] * il0, a1 = o[j][1] * il0;
        float b0 = o[j][2] * il1, b1 = o[j][3] * il1;
        __half h0,lo0,h1,lo1;
        split2h(a0,h0,lo0); split2h(a1,h1,lo1);
        *(__half2*)(zh + (size_t)row0 * DD + c) = __halves2half2(h0, h1);
        *(__half2*)(zl + (size_t)row0 * DD + c) = __halves2half2(lo0, lo1);
        split2h(b0,h0,lo0); split2h(b1,h1,lo1);
        *(__half2*)(zh + (size_t)(row0 + 8) * DD + c) = __halves2half2(h0, h1);
        *(__half2*)(zl + (size_t)(row0 + 8) * DD + c) = __halves2half2(lo0, lo1);
    }
}

// ---------------------------------------------------------------------------
// Host launcher
// ---------------------------------------------------------------------------
extern "C" void kernel_launch(void* const* d_in, const int* in_sizes, int n_in,
                              void* d_out, int out_size)
{
    (void)in_sizes; (void)n_in; (void)out_size;
    const float* resid = (const float*)d_in[0];
    const float* ln1w  = (const float*)d_in[1];
    const float* ln1b  = (const float*)d_in[2];
    const float* WQ    = (const float*)d_in[3];
    const float* bQ    = (const float*)d_in[4];
    const float* WK    = (const float*)d_in[5];
    const float* bK    = (const float*)d_in[6];
    const float* WV    = (const float*)d_in[7];
    const float* bV    = (const float*)d_in[8];
    const float* WO    = (const float*)d_in[9];
    const float* bO    = (const float*)d_in[10];
    const float* ln2w  = (const float*)d_in[11];
    const float* ln2b  = (const float*)d_in[12];
    const float* Win   = (const float*)d_in[13];
    const float* bin   = (const float*)d_in[14];
    const float* Wout  = (const float*)d_in[15];
    const float* bout  = (const float*)d_in[16];

    float *mid, *biasqkv;
    bf16 *xh, *xl, *qkvh_, *qkvl_, *acth, *actl, *wh;
    cudaGetSymbolAddress((void**)&mid,   g_mid);
    cudaGetSymbolAddress((void**)&biasqkv, g_bias);
    cudaGetSymbolAddress((void**)&xh,    g_xh);
    cudaGetSymbolAddress((void**)&xl,    g_xl);
    cudaGetSymbolAddress((void**)&qkvh_, g_qkvh);
    cudaGetSymbolAddress((void**)&qkvl_, g_qkvl);
    cudaGetSymbolAddress((void**)&acth,  g_acth);
    cudaGetSymbolAddress((void**)&actl,  g_actl);
    cudaGetSymbolAddress((void**)&wh,    g_wh);

    // fp16 aliases
    __half* x16h   = (__half*)xh;
    __half* x16l   = (__half*)xl;
    __half* qkv16h = (__half*)qkvh_;
    __half* qkv16l = (__half*)qkvl_;
    __half* a16h   = (__half*)acth;
    __half* a16l   = (__half*)actl;
    __half* w16    = (__half*)wh;

    cudaFuncSetAttribute(attn_mma, cudaFuncAttributeMaxDynamicSharedMemorySize,
                         ATTN_SMEM);
    cudaFuncSetAttribute(gemm_f16<EPI_QKV16>,
                         cudaFuncAttributeMaxDynamicSharedMemorySize, GEMM2_SMEM);
    cudaFuncSetAttribute(gemm_f16<EPI_GELU16>,
                         cudaFuncAttributeMaxDynamicSharedMemorySize, GEMM2_SMEM);
    cudaFuncSetAttribute(gemm_f16<EPI_RES32>,
                         cudaFuncAttributeMaxDynamicSharedMemorySize, GEMM2_SMEM);

    dim3 tb(32, 8);

    // 1) LN1 -> fp16 split
    ln_split_kernel<<<NTOK, 256>>>(resid, ln1w, ln1b, x16h, x16l);

    // 2) fused QKV (2-term fp16; Q prescaled by 1/8)
    concat_bias<<<12, 256>>>(bQ, bK, bV, biasqkv);
    tsplit16_qkv<<<dim3(DHH/32, DD/32, 48), tb>>>(WQ, WK, WV, w16);
    gemm_f16<EPI_QKV16><<<dim3(3*DD/128, NTOK/128), 256, GEMM2_SMEM>>>(
        x16h, x16l, w16, biasqkv, nullptr, nullptr, qkv16h, qkv16l,
        NTOK, 3*DD, DD);

    // 3) attention (fp16, 2-term) -> z fp16 split (into x16h/x16l)
    dim3 ga(SS / 64, BB * HH);
    attn_mma<<<ga, 128, ATTN_SMEM>>>(qkv16h, qkv16l, x16h, x16l);

    // 4) O-projection + residual -> mid (2-term fp16)
    tsplit16_kernel<<<dim3(DD/32, DD/32), tb>>>(WO, w16, DD, DD);
    gemm_f16<EPI_RES32><<<dim3(DD/128, NTOK/128), 256, GEMM2_SMEM>>>(
        x16h, x16l, w16, bO, resid, mid, nullptr, nullptr, NTOK, DD, DD);

    // 5) LN2 -> fp16 split
    ln_split_kernel<<<NTOK, 256>>>(mid, ln2w, ln2b, x16h, x16l);

    // 6) MLP in + exact GELU -> fp16 split act (2-term fp16)
    tsplit16_kernel<<<dim3(DMM/32, DD/32), tb>>>(Win, w16, DD, DMM);
    gemm_f16<EPI_GELU16><<<dim3(DMM/128, NTOK/128), 256, GEMM2_SMEM>>>(
        x16h, x16l, w16, bin, nullptr, nullptr, a16h, a16l, NTOK, DMM, DD);

    // 7) MLP out + bias + residual -> d_out (2-term fp16)
    tsplit16_kernel<<<dim3(DD/32, DMM/32), tb>>>(Wout, w16, DMM, DD);
    gemm_f16<EPI_RES32><<<dim3(DD/128, NTOK/128), 256, GEMM2_SMEM>>>(
        a16h, a16l, w16, bout, mid, (float*)d_out, nullptr, nullptr,
        NTOK, DD, DMM);
}

// round 15
// speedup vs baseline: 1.7378x; 1.2473x over previous
#include <cuda_runtime.h>
#include <cuda_bf16.h>
#include <cuda_fp16.h>
#include <math.h>
#include <stdint.h>

// Problem constants
#define BB   2
#define SS   2048
#define DD   1024
#define HH   16
#define DHH  64
#define DMM  4096
#define NTOK (BB*SS)          // 4096
#define EPSLN 1e-5f

typedef __nv_bfloat16  bf16;

// ---------------------------------------------------------------------------
// Device scratch (2-byte buffers, fp16 phase)
// ---------------------------------------------------------------------------
__device__ float g_mid[NTOK*DD];
__device__ float g_bias[3*DD];        // concatenated QKV bias
__device__ bf16  g_xh [NTOK*DD];      // split activations hi (fp16)
__device__ bf16  g_xl [NTOK*DD];      // split activations lo (fp16)
__device__ bf16  g_qkvh[NTOK*3*DD];   // fused QKV output (hi, fp16)
__device__ bf16  g_qkvl[NTOK*3*DD];   // fused QKV output (lo, fp16)
__device__ bf16  g_acth[NTOK*DMM];    // gelu output (single fp16)
__device__ bf16  g_wh [DD*DMM];       // single transposed weight (fp16)

// ---------------------------------------------------------------------------
// Helpers
// ---------------------------------------------------------------------------
__device__ __forceinline__ void split2h(float x, __half& h, __half& l)
{
    h = __float2half_rn(x);
    l = __float2half_rn(x - __half2float(h));
}

__device__ __forceinline__ uint32_t cvta_s(const void* p)
{
    return (uint32_t)__cvta_generic_to_shared(p);
}

__device__ __forceinline__ void cp16(uint32_t s, const void* g)
{
    asm volatile("cp.async.cg.shared.global [%0], [%1], 16;" :: "r"(s), "l"(g));
}

__device__ __forceinline__ void ldsm4(unsigned r[4], uint32_t a)
{
    asm volatile("ldmatrix.sync.aligned.m8n8.x4.shared.b16 {%0,%1,%2,%3}, [%4];"
                 : "=r"(r[0]), "=r"(r[1]), "=r"(r[2]), "=r"(r[3]) : "r"(a));
}

__device__ __forceinline__ void ldsm4t(unsigned r[4], uint32_t a)
{
    asm volatile("ldmatrix.sync.aligned.m8n8.x4.trans.shared.b16 {%0,%1,%2,%3}, [%4];"
                 : "=r"(r[0]), "=r"(r[1]), "=r"(r[2]), "=r"(r[3]) : "r"(a));
}

// fp16 inputs, fp32 accumulator
__device__ __forceinline__ void mma16816h(float c[4], const unsigned a[4],
                                          const unsigned b[2])
{
    asm volatile(
        "mma.sync.aligned.m16n8k16.row.col.f32.f16.f16.f32 "
        "{%0,%1,%2,%3}, {%4,%5,%6,%7}, {%8,%9}, {%0,%1,%2,%3};"
        : "+f"(c[0]), "+f"(c[1]), "+f"(c[2]), "+f"(c[3])
        : "r"(a[0]), "r"(a[1]), "r"(a[2]), "r"(a[3]), "r"(b[0]), "r"(b[1]));
}

__device__ __forceinline__ float gelu_exact(float x)
{
    return 0.5f * x * (1.0f + erff(x * 0.70710678118654752f));
}

// ---------------------------------------------------------------------------
// LayerNorm kernels. Split variant (hi/lo) and single-fp16 variant.
// ---------------------------------------------------------------------------
__device__ __forceinline__ void ln_core(const float* __restrict__ x,
                                        const float* __restrict__ w,
                                        const float* __restrict__ b,
                                        int row, int tid, int lane, int warp,
                                        float* red, float* bcast,
                                        float out[4])
{
    float4 v = ((const float4*)(x + (size_t)row * DD))[tid];

    float s = v.x + v.y + v.z + v.w;
    #pragma unroll
    for (int o = 16; o > 0; o >>= 1) s += __shfl_xor_sync(0xffffffffu, s, o);
    if (lane == 0) red[warp] = s;
    __syncthreads();
    if (tid < 8) {
        float t = red[tid];
        #pragma unroll
        for (int o = 4; o > 0; o >>= 1) t += __shfl_xor_sync(0xffu, t, o);
        if (tid == 0) *bcast = t;
    }
    __syncthreads();
    const float mean = *bcast * (1.0f / DD);
    __syncthreads();

    float dx0 = v.x - mean, dx1 = v.y - mean, dx2 = v.z - mean, dx3 = v.w - mean;
    float sq = dx0*dx0 + dx1*dx1 + dx2*dx2 + dx3*dx3;
    #pragma unroll
    for (int o = 16; o > 0; o >>= 1) sq += __shfl_xor_sync(0xffffffffu, sq, o);
    if (lane == 0) red[warp] = sq;
    __syncthreads();
    if (tid < 8) {
        float t = red[tid];
        #pragma unroll
        for (int o = 4; o > 0; o >>= 1) t += __shfl_xor_sync(0xffu, t, o);
        if (tid == 0) *bcast = t;
    }
    __syncthreads();
    const float inv = rsqrtf(*bcast * (1.0f / DD) + EPSLN);

    float4 wv = ((const float4*)w)[tid];
    float4 bv = ((const float4*)b)[tid];
    out[0] = dx0 * inv * wv.x + bv.x;
    out[1] = dx1 * inv * wv.y + bv.y;
    out[2] = dx2 * inv * wv.z + bv.z;
    out[3] = dx3 * inv * wv.w + bv.w;
}

__global__ __launch_bounds__(256)
void ln_split_kernel(const float* __restrict__ x, const float* __restrict__ w,
                     const float* __restrict__ b, __half* __restrict__ oh,
                     __half* __restrict__ ol)
{
    __shared__ float red[8];
    __shared__ float bcast;
    const int row = blockIdx.x, tid = threadIdx.x;
    float o[4];
    ln_core(x, w, b, row, tid, tid & 31, tid >> 5, red, &bcast, o);

    __half h0,h1,h2,h3,l0,l1,l2,l3;
    split2h(o[0],h0,l0); split2h(o[1],h1,l1);
    split2h(o[2],h2,l2); split2h(o[3],h3,l3);
    __half2* H = (__half2*)(oh + (size_t)row * DD + tid * 4);
    __half2* L = (__half2*)(ol + (size_t)row * DD + tid * 4);
    H[0] = __halves2half2(h0, h1); H[1] = __halves2half2(h2, h3);
    L[0] = __halves2half2(l0, l1); L[1] = __halves2half2(l2, l3);
}

__global__ __launch_bounds__(256)
void ln_single_kernel(const float* __restrict__ x, const float* __restrict__ w,
                      const float* __restrict__ b, __half* __restrict__ oh)
{
    __shared__ float red[8];
    __shared__ float bcast;
    const int row = blockIdx.x, tid = threadIdx.x;
    float o[4];
    ln_core(x, w, b, row, tid, tid & 31, tid >> 5, red, &bcast, o);

    __half2* H = (__half2*)(oh + (size_t)row * DD + tid * 4);
    H[0] = __halves2half2(__float2half_rn(o[0]), __float2half_rn(o[1]));
    H[1] = __halves2half2(__float2half_rn(o[2]), __float2half_rn(o[3]));
}

// ---------------------------------------------------------------------------
// Concatenate QKV biases into g_bias[3072]
// ---------------------------------------------------------------------------
__global__ void concat_bias(const float* __restrict__ bq,
                            const float* __restrict__ bk,
                            const float* __restrict__ bv,
                            float* __restrict__ out)
{
    int i = blockIdx.x * blockDim.x + threadIdx.x;
    float v;
    if (i < DD) v = bq[i];
    else if (i < 2*DD) v = bk[i - DD];
    else v = bv[i - 2*DD];
    out[i] = v;
}

// ---------------------------------------------------------------------------
// Transpose + single-fp16 convert: o16[c*R + r] = fp16(in[r][c])
// ---------------------------------------------------------------------------
__global__ __launch_bounds__(256)
void tsplit16_kernel(const float* __restrict__ in, __half* __restrict__ o16,
                     int R, int C)
{
    __shared__ float t[32][33];
    const int tx = threadIdx.x, ty = threadIdx.y;
    const int c0 = blockIdx.x * 32, r0 = blockIdx.y * 32;
    #pragma unroll
    for (int i = 0; i < 4; i++)
        t[ty + 8*i][tx] = in[(size_t)(r0 + ty + 8*i) * C + c0 + tx];
    __syncthreads();
    #pragma unroll
    for (int i = 0; i < 4; i++) {
        int c = c0 + ty + 8*i;
        o16[(size_t)c * R + r0 + tx] = __float2half_rn(t[tx][ty + 8*i]);
    }
}

// ---------------------------------------------------------------------------
// Transpose + single-fp16 for QKV weights
// ---------------------------------------------------------------------------
__global__ __launch_bounds__(256)
void tsplit16_qkv(const float* __restrict__ wq, const float* __restrict__ wk,
                  const float* __restrict__ wv, __half* __restrict__ o16)
{
    __shared__ float t[32][33];
    const int tx = threadIdx.x, ty = threadIdx.y;
    const int c0 = blockIdx.x * 32, r0 = blockIdx.y * 32;
    const int z = blockIdx.z;
    const int which = z >> 4, h = z & 15;
    const float* src = (which == 0 ? wq : (which == 1 ? wk : wv))
                       + (size_t)h * DD * DHH;
    #pragma unroll
    for (int i = 0; i < 4; i++)
        t[ty + 8*i][tx] = src[(size_t)(r0 + ty + 8*i) * DHH + c0 + tx];
    __syncthreads();
    #pragma unroll
    for (int i = 0; i < 4; i++) {
        int c = c0 + ty + 8*i;
        size_t n = (size_t)which * DD + h * DHH + c;
        o16[n * DD + r0 + tx] = __float2half_rn(t[tx][ty + 8*i]);
    }
}

// ---------------------------------------------------------------------------
// Common GEMM machinery
// ---------------------------------------------------------------------------
#define EPI_GELU16 1
#define EPI_RES32  2
#define EPI_QKV16  3

#define TILE_BYTES 8192             // 128 rows * 64B

// ---------------------------------------------------------------------------
// 2-term split-fp16 GEMM: C = (Ah + Al) @ B16  (QKV, O-proj)
// ---------------------------------------------------------------------------
#define STG2_BYTES (3*TILE_BYTES)   // Ah, Al, B = 24KB
#define GEMM2_SMEM (3*STG2_BYTES)   // 73728 B

template <int EPI>
__global__ __launch_bounds__(256, 2)
void gemm_f16(const __half* __restrict__ Ah, const __half* __restrict__ Al,
              const __half* __restrict__ Bm,
              const float* __restrict__ bias, const float* __restrict__ Rm,
              float* __restrict__ Cf, __half* __restrict__ Oh,
              __half* __restrict__ Ol, int M, int N, int K)
{
    extern __shared__ bf16 sm[];
    const int tid = threadIdx.x;
    const int bx = blockIdx.x, by = blockIdx.y;
    const int warp = tid >> 5, lane = tid & 31;
    const int wm = warp >> 1, wn = warp & 1;

    const int lrow = tid >> 1;
    const int lhalf = (tid & 1);
    const __half* gAh = Ah + (size_t)(by * 128 + lrow) * K + lhalf * 16;
    const __half* gAl = Al + (size_t)(by * 128 + lrow) * K + lhalf * 16;
    const __half* gB  = Bm + (size_t)(bx * 128 + lrow) * K + lhalf * 16;
    const uint32_t sbase = cvta_s(sm);
    const uint32_t lxm = (uint32_t)((lrow & 6) << 3);
    const uint32_t lso0 = lrow * 64 + ((lhalf * 32)      ^ lxm);
    const uint32_t lso1 = lrow * 64 + ((lhalf * 32 + 16) ^ lxm);

    float acc[2][8][4];
    #pragma unroll
    for (int i = 0; i < 2; i++)
        #pragma unroll
        for (int j = 0; j < 8; j++)
            #pragma unroll
            for (int q = 0; q < 4; q++) acc[i][j][q] = 0.0f;

    const int a_r = (lane & 7) + ((lane >> 3) & 1) * 8;
    const int a_c = (lane >> 4) * 8;
    const int b_r = (lane & 7) + (lane >> 4) * 8;
    const int b_c = ((lane >> 3) & 1) * 8;

    uint32_t arow[2], axm[2];
    #pragma unroll
    for (int mf = 0; mf < 2; mf++) {
        int r = wm*32 + mf*16 + a_r;
        arow[mf] = (uint32_t)r * 64;
        axm[mf]  = (uint32_t)((r & 6) << 3);
    }
    uint32_t brow[4], bxm[4];
    #pragma unroll
    for (int p = 0; p < 4; p++) {
        int r = wn*64 + p*16 + b_r;
        brow[p] = (uint32_t)r * 64;
        bxm[p]  = (uint32_t)((r & 6) << 3);
    }
    const uint32_t acb = (uint32_t)(a_c * 2);
    const uint32_t bcb = (uint32_t)(b_c * 2);

    const int T = K / 32;

    auto issue = [&](int s, int kk) {
        uint32_t st = sbase + (uint32_t)s * STG2_BYTES;
        cp16(st + lso0,                gAh + kk);
        cp16(st + lso1,                gAh + kk + 8);
        cp16(st + TILE_BYTES   + lso0, gAl + kk);
        cp16(st + TILE_BYTES   + lso1, gAl + kk + 8);
        cp16(st + TILE_BYTES*2 + lso0, gB  + kk);
        cp16(st + TILE_BYTES*2 + lso1, gB  + kk + 8);
        asm volatile("cp.async.commit_group;");
    };

    issue(0, 0);
    if (T > 1) issue(1, 32);

    int stage = 0;
    for (int t = 0; t < T; t++) {
        if (t + 2 < T) {
            issue((stage + 2) % 3, (t + 2) * 32);
            asm volatile("cp.async.wait_group 2;");
        } else if (t + 1 < T) {
            asm volatile("cp.async.wait_group 1;");
        } else {
            asm volatile("cp.async.wait_group 0;");
        }
        __syncthreads();

        const uint32_t st  = sbase + (uint32_t)stage * STG2_BYTES;
        const uint32_t sAh = st;
        const uint32_t sAl = st + TILE_BYTES;
        const uint32_t sB  = st + TILE_BYTES*2;

        #pragma unroll
        for (int kc = 0; kc < 2; kc++) {
            const uint32_t kb = (uint32_t)(kc * 32);
            unsigned ah[2][4], al[2][4];
            #pragma unroll
            for (int mf = 0; mf < 2; mf++) {
                uint32_t ao = arow[mf] + ((kb + acb) ^ axm[mf]);
                ldsm4(ah[mf], sAh + ao);
                ldsm4(al[mf], sAl + ao);
            }
            #pragma unroll
            for (int p = 0; p < 4; p++) {
                unsigned b4[4];
                uint32_t bo = brow[p] + ((kb + bcb) ^ bxm[p]);
                ldsm4(b4, sB + bo);
                #pragma unroll
                for (int mf = 0; mf < 2; mf++) {
                    mma16816h(acc[mf][2*p],     ah[mf], b4);
                    mma16816h(acc[mf][2*p + 1], ah[mf], b4 + 2);
                    mma16816h(acc[mf][2*p],     al[mf], b4);
                    mma16816h(acc[mf][2*p + 1], al[mf], b4 + 2);
                }
            }
        }
        __syncthreads();
        stage = (stage + 1) % 3;
    }

    const int er = by * 128 + wm * 32 + (lane >> 2);
    const int ec = bx * 128 + wn * 64 + (lane & 3) * 2;
    #pragma unroll
    for (int mf = 0; mf < 2; mf++) {
        #pragma unroll
        for (int nf = 0; nf < 8; nf++) {
            int c = ec + nf * 8;
            float b0 = bias[c], b1 = bias[c + 1];
            #pragma unroll
            for (int half = 0; half < 2; half++) {
                int r = er + mf * 16 + half * 8;
                float v0 = acc[mf][nf][half * 2 + 0] + b0;
                float v1 = acc[mf][nf][half * 2 + 1] + b1;
                if (EPI == EPI_QKV16) {
                    float sc = (c < DD) ? 0.125f : 1.0f;
                    v0 *= sc; v1 *= sc;
                    __half h0,h1,l0,l1;
                    split2h(v0,h0,l0); split2h(v1,h1,l1);
                    *(__half2*)(Oh + (size_t)r * N + c) = __halves2half2(h0, h1);
                    *(__half2*)(Ol + (size_t)r * N + c) = __halves2half2(l0, l1);
                } else {
                    float2 rr = *(const float2*)(Rm + (size_t)r * N + c);
                    v0 += rr.x; v1 += rr.y;
                    float2 o; o.x = v0; o.y = v1;
                    *(float2*)(Cf + (size_t)r * N + c) = o;
                }
            }
        }
    }
}

// ---------------------------------------------------------------------------
// 1-term fp16 GEMM: C = A16 @ B16 (f32 acc).  MLP-in (GELU) and MLP-out (res).
// ---------------------------------------------------------------------------
#define STG1_BYTES (2*TILE_BYTES)   // A, B = 16KB
#define GEMM1_SMEM (3*STG1_BYTES)   // 49152 B

template <int EPI>
__global__ __launch_bounds__(256, 2)
void gemm_f16_1t(const __half* __restrict__ Am, const __half* __restrict__ Bm,
                 const float* __restrict__ bias, const float* __restrict__ Rm,
                 float* __restrict__ Cf, __half* __restrict__ Oh,
                 int M, int N, int K)
{
    extern __shared__ bf16 sm[];
    const int tid = threadIdx.x;
    const int bx = blockIdx.x, by = blockIdx.y;
    const int warp = tid >> 5, lane = tid & 31;
    const int wm = warp >> 1, wn = warp & 1;

    const int lrow = tid >> 1;
    const int lhalf = (tid & 1);
    const __half* gA = Am + (size_t)(by * 128 + lrow) * K + lhalf * 16;
    const __half* gB = Bm + (size_t)(bx * 128 + lrow) * K + lhalf * 16;
    const uint32_t sbase = cvta_s(sm);
    const uint32_t lxm = (uint32_t)((lrow & 6) << 3);
    const uint32_t lso0 = lrow * 64 + ((lhalf * 32)      ^ lxm);
    const uint32_t lso1 = lrow * 64 + ((lhalf * 32 + 16) ^ lxm);

    float acc[2][8][4];
    #pragma unroll
    for (int i = 0; i < 2; i++)
        #pragma unroll
        for (int j = 0; j < 8; j++)
            #pragma unroll
            for (int q = 0; q < 4; q++) acc[i][j][q] = 0.0f;

    const int a_r = (lane & 7) + ((lane >> 3) & 1) * 8;
    const int a_c = (lane >> 4) * 8;
    const int b_r = (lane & 7) + (lane >> 4) * 8;
    const int b_c = ((lane >> 3) & 1) * 8;

    uint32_t arow[2], axm[2];
    #pragma unroll
    for (int mf = 0; mf < 2; mf++) {
        int r = wm*32 + mf*16 + a_r;
        arow[mf] = (uint32_t)r * 64;
        axm[mf]  = (uint32_t)((r & 6) << 3);
    }
    uint32_t brow[4], bxm[4];
    #pragma unroll
    for (int p = 0; p < 4; p++) {
        int r = wn*64 + p*16 + b_r;
        brow[p] = (uint32_t)r * 64;
        bxm[p]  = (uint32_t)((r & 6) << 3);
    }
    const uint32_t acb = (uint32_t)(a_c * 2);
    const uint32_t bcb = (uint32_t)(b_c * 2);

    const int T = K / 32;

    auto issue = [&](int s, int kk) {
        uint32_t st = sbase + (uint32_t)s * STG1_BYTES;
        cp16(st + lso0,              gA + kk);
        cp16(st + lso1,              gA + kk + 8);
        cp16(st + TILE_BYTES + lso0, gB + kk);
        cp16(st + TILE_BYTES + lso1, gB + kk + 8);
        asm volatile("cp.async.commit_group;");
    };

    issue(0, 0);
    if (T > 1) issue(1, 32);

    int stage = 0;
    for (int t = 0; t < T; t++) {
        if (t + 2 < T) {
            issue((stage + 2) % 3, (t + 2) * 32);
            asm volatile("cp.async.wait_group 2;");
        } else if (t + 1 < T) {
            asm volatile("cp.async.wait_group 1;");
        } else {
            asm volatile("cp.async.wait_group 0;");
        }
        __syncthreads();

        const uint32_t st = sbase + (uint32_t)stage * STG1_BYTES;
        const uint32_t sA = st;
        const uint32_t sB = st + TILE_BYTES;

        #pragma unroll
        for (int kc = 0; kc < 2; kc++) {
            const uint32_t kb = (uint32_t)(kc * 32);
            unsigned a4[2][4];
            #pragma unroll
            for (int mf = 0; mf < 2; mf++) {
                uint32_t ao = arow[mf] + ((kb + acb) ^ axm[mf]);
                ldsm4(a4[mf], sA + ao);
            }
            #pragma unroll
            for (int p = 0; p < 4; p++) {
                unsigned b4[4];
                uint32_t bo = brow[p] + ((kb + bcb) ^ bxm[p]);
                ldsm4(b4, sB + bo);
                #pragma unroll
                for (int mf = 0; mf < 2; mf++) {
                    mma16816h(acc[mf][2*p],     a4[mf], b4);
                    mma16816h(acc[mf][2*p + 1], a4[mf], b4 + 2);
                }
            }
        }
        __syncthreads();
        stage = (stage + 1) % 3;
    }

    const int er = by * 128 + wm * 32 + (lane >> 2);
    const int ec = bx * 128 + wn * 64 + (lane & 3) * 2;
    #pragma unroll
    for (int mf = 0; mf < 2; mf++) {
        #pragma unroll
        for (int nf = 0; nf < 8; nf++) {
            int c = ec + nf * 8;
            float b0 = bias[c], b1 = bias[c + 1];
            #pragma unroll
            for (int half = 0; half < 2; half++) {
                int r = er + mf * 16 + half * 8;
                float v0 = acc[mf][nf][half * 2 + 0] + b0;
                float v1 = acc[mf][nf][half * 2 + 1] + b1;
                if (EPI == EPI_GELU16) {
                    v0 = gelu_exact(v0); v1 = gelu_exact(v1);
                    *(__half2*)(Oh + (size_t)r * N + c) =
                        __halves2half2(__float2half_rn(v0), __float2half_rn(v1));
                } else {
                    float2 rr = *(const float2*)(Rm + (size_t)r * N + c);
                    v0 += rr.x; v1 += rr.y;
                    float2 o; o.x = v0; o.y = v1;
                    *(float2*)(Cf + (size_t)r * N + c) = o;
                }
            }
        }
    }
}

// ---------------------------------------------------------------------------
// Tensor-core flash attention, fp16:
//   S = (Qh + Ql) @ Kh^T  (2-term)     O = Ph @ Vh  (1-term)
// ---------------------------------------------------------------------------
#define AQS   72
#define ATILE (64*AQS)
#define ATTN_SMEM ((2*ATILE + 2*2*ATILE) * 2)   // Qh,Ql + 2 stages * {Kh,Vh}

__global__ __launch_bounds__(128, 2)
void attn_mma(const __half* __restrict__ qkvh, const __half* __restrict__ qkvl,
              __half* __restrict__ zh, __half* __restrict__ zl)
{
    extern __shared__ bf16 smb[];
    const uint32_t sbase = cvta_s(smb);
    const int tid  = threadIdx.x;
    const int warp = tid >> 5, lane = tid & 31;
    const int qt = blockIdx.x;
    const int bh = blockIdx.y;
    const int h  = bh & 15;
    const int hcol = h * DHH;
    const int tokbase = (bh >> 4) * SS;

    const uint32_t oQh = 0, oQl = ATILE;
    auto stageoff = [](int s) { return (uint32_t)(2*ATILE + s*2*ATILE); };

    const int ldrow = tid >> 1;
    const int ldc0  = (tid & 1) * 32;
    auto ld_tensor = [&](uint32_t selems, const __half* g, int tok0, int coff) {
        const __half* gp = g + (size_t)(tok0 + ldrow) * (3*DD) + coff + ldc0;
        uint32_t sp = sbase + (selems + ldrow * AQS + ldc0) * 2;
        cp16(sp,      gp);
        cp16(sp + 16, gp + 8);
        cp16(sp + 32, gp + 16);
        cp16(sp + 48, gp + 24);
    };
    auto issue_kv = [&](int s, int kt) {
        int tok0 = tokbase + kt * 64;
        uint32_t so = stageoff(s);
        ld_tensor(so,           qkvh, tok0, DD   + hcol);   // Kh
        ld_tensor(so + ATILE,   qkvh, tok0, 2*DD + hcol);   // Vh
        asm volatile("cp.async.commit_group;");
    };

    {
        int tok0 = tokbase + qt * 64;
        ld_tensor(oQh, qkvh, tok0, hcol);
        ld_tensor(oQl, qkvl, tok0, hcol);
        issue_kv(0, 0);
    }

    const int a_r  = (lane & 7) + ((lane >> 3) & 1) * 8;
    const int a_c  = (lane >> 4) * 8;
    const int kb_r = (lane & 7) + (lane >> 4) * 8;
    const int kb_c = ((lane >> 3) & 1) * 8;
    const int vb_r = (lane & 7) + ((lane >> 3) & 1) * 8;
    const int vb_c = (lane >> 4) * 8;

    unsigned qh[4][4], ql[4][4];
    float o[8][4];
    #pragma unroll
    for (int j = 0; j < 8; j++)
        #pragma unroll
        for (int q = 0; q < 4; q++) o[j][q] = 0.0f;
    float m0 = -INFINITY, m1 = -INFINITY, l0 = 0.0f, l1 = 0.0f;

    const int r0 = lane >> 2;
    const int colq = 2 * (lane & 3);

    for (int kt = 0; kt <= qt; kt++) {
        if (kt + 1 <= qt) {
            issue_kv((kt + 1) & 1, kt + 1);
            asm volatile("cp.async.wait_group 1;");
        } else {
            asm volatile("cp.async.wait_group 0;");
        }
        __syncthreads();

        if (kt == 0) {
            #pragma unroll
            for (int kc = 0; kc < 4; kc++) {
                uint32_t ao = ((warp*16 + a_r) * AQS + kc*16 + a_c) * 2;
                ldsm4(qh[kc], sbase + (oQh)*2 + ao);
                ldsm4(ql[kc], sbase + (oQl)*2 + ao);
            }
        }

        const uint32_t so = stageoff(kt & 1);
        const uint32_t sKh = sbase + so * 2;
        const uint32_t sVh = sbase + (so + ATILE) * 2;

        // ---- S = (Qh + Ql) @ Kh^T ----
        float s[8][4];
        #pragma unroll
        for (int j = 0; j < 8; j++)
            #pragma unroll
            for (int q = 0; q < 4; q++) s[j][q] = 0.0f;

        #pragma unroll
        for (int jp = 0; jp < 4; jp++) {
            #pragma unroll
            for (int kc = 0; kc < 4; kc++) {
                unsigned kh4[4];
                uint32_t ko = ((jp*16 + kb_r) * AQS + kc*16 + kb_c) * 2;
                ldsm4(kh4, sKh + ko);
                mma16816h(s[2*jp],   qh[kc], kh4);
                mma16816h(s[2*jp+1], qh[kc], kh4 + 2);
                mma16816h(s[2*jp],   ql[kc], kh4);
                mma16816h(s[2*jp+1], ql[kc], kh4 + 2);
            }
        }

        if (kt == qt) {
            const int rg0 = warp*16 + r0;
            #pragma unroll
            for (int j = 0; j < 8; j++) {
                int cg = j*8 + colq;
                if (cg     > rg0) s[j][0] = -1e30f;
                if (cg + 1 > rg0) s[j][1] = -1e30f;
                if (cg     > rg0 + 8) s[j][2] = -1e30f;
                if (cg + 1 > rg0 + 8) s[j][3] = -1e30f;
            }
        }

        float vmax0 = -INFINITY, vmax1 = -INFINITY;
        #pragma unroll
        for (int j = 0; j < 8; j++) {
            vmax0 = fmaxf(vmax0, fmaxf(s[j][0], s[j][1]));
            vmax1 = fmaxf(vmax1, fmaxf(s[j][2], s[j][3]));
        }
        vmax0 = fmaxf(vmax0, __shfl_xor_sync(0xffffffffu, vmax0, 1));
        vmax0 = fmaxf(vmax0, __shfl_xor_sync(0xffffffffu, vmax0, 2));
        vmax1 = fmaxf(vmax1, __shfl_xor_sync(0xffffffffu, vmax1, 1));
        vmax1 = fmaxf(vmax1, __shfl_xor_sync(0xffffffffu, vmax1, 2));

        float mn0 = fmaxf(m0, vmax0), mn1 = fmaxf(m1, vmax1);
        float f0 = __expf(m0 - mn0), f1 = __expf(m1 - mn1);
        m0 = mn0; m1 = mn1;

        float rs0 = 0.0f, rs1 = 0.0f;
        #pragma unroll
        for (int j = 0; j < 8; j++) {
            s[j][0] = __expf(s[j][0] - mn0);
            s[j][1] = __expf(s[j][1] - mn0);
            s[j][2] = __expf(s[j][2] - mn1);
            s[j][3] = __expf(s[j][3] - mn1);
            rs0 += s[j][0] + s[j][1];
            rs1 += s[j][2] + s[j][3];
        }
        rs0 += __shfl_xor_sync(0xffffffffu, rs0, 1);
        rs0 += __shfl_xor_sync(0xffffffffu, rs0, 2);
        rs1 += __shfl_xor_sync(0xffffffffu, rs1, 1);
        rs1 += __shfl_xor_sync(0xffffffffu, rs1, 2);
        l0 = l0 * f0 + rs0;
        l1 = l1 * f1 + rs1;

        #pragma unroll
        for (int j = 0; j < 8; j++) {
            o[j][0] *= f0; o[j][1] *= f0;
            o[j][2] *= f1; o[j][3] *= f1;
        }

        // ---- repack P (hi only) into fp16 A fragments ----
        unsigned ph[4][4];
        #pragma unroll
        for (int jc = 0; jc < 4; jc++) {
            const int j0 = 2*jc, j1 = 2*jc + 1;
            __half2 t0 = __halves2half2(__float2half_rn(s[j0][0]),
                                        __float2half_rn(s[j0][1]));
            __half2 t1 = __halves2half2(__float2half_rn(s[j0][2]),
                                        __float2half_rn(s[j0][3]));
            __half2 t2 = __halves2half2(__float2half_rn(s[j1][0]),
                                        __float2half_rn(s[j1][1]));
            __half2 t3 = __halves2half2(__float2half_rn(s[j1][2]),
                                        __float2half_rn(s[j1][3]));
            ph[jc][0] = *reinterpret_cast<unsigned*>(&t0);
            ph[jc][1] = *reinterpret_cast<unsigned*>(&t1);
            ph[jc][2] = *reinterpret_cast<unsigned*>(&t2);
            ph[jc][3] = *reinterpret_cast<unsigned*>(&t3);
        }

        // ---- O += Ph @ Vh ----
        #pragma unroll
        for (int jc = 0; jc < 4; jc++) {
            #pragma unroll
            for (int np = 0; np < 4; np++) {
                unsigned vh4[4];
                uint32_t vo = ((jc*16 + vb_r) * AQS + np*16 + vb_c) * 2;
                ldsm4t(vh4, sVh + vo);
                mma16816h(o[2*np],   ph[jc], vh4);
                mma16816h(o[2*np+1], ph[jc], vh4 + 2);
            }
        }
        __syncthreads();
    }

    const float il0 = 1.0f / l0, il1 = 1.0f / l1;
    const int row0 = tokbase + qt*64 + warp*16 + r0;
    #pragma unroll
    for (int j = 0; j < 8; j++) {
        int c = hcol + j*8 + colq;
        float a0 = o[j][0] * il0, a1 = o[j][1] * il0;
        float b0 = o[j][2] * il1, b1 = o[j][3] * il1;
        __half h0,lo0,h1,lo1;
        split2h(a0,h0,lo0); split2h(a1,h1,lo1);
        *(__half2*)(zh + (size_t)row0 * DD + c) = __halves2half2(h0, h1);
        *(__half2*)(zl + (size_t)row0 * DD + c) = __halves2half2(lo0, lo1);
        split2h(b0,h0,lo0); split2h(b1,h1,lo1);
        *(__half2*)(zh + (size_t)(row0 + 8) * DD + c) = __halves2half2(h0, h1);
        *(__half2*)(zl + (size_t)(row0 + 8) * DD + c) = __halves2half2(lo0, lo1);
    }
}

// ---------------------------------------------------------------------------
// Host launcher
// ---------------------------------------------------------------------------
extern "C" void kernel_launch(void* const* d_in, const int* in_sizes, int n_in,
                              void* d_out, int out_size)
{
    (void)in_sizes; (void)n_in; (void)out_size;
    const float* resid = (const float*)d_in[0];
    const float* ln1w  = (const float*)d_in[1];
    const float* ln1b  = (const float*)d_in[2];
    const float* WQ    = (const float*)d_in[3];
    const float* bQ    = (const float*)d_in[4];
    const float* WK    = (const float*)d_in[5];
    const float* bK    = (const float*)d_in[6];
    const float* WV    = (const float*)d_in[7];
    const float* bV    = (const float*)d_in[8];
    const float* WO    = (const float*)d_in[9];
    const float* bO    = (const float*)d_in[10];
    const float* ln2w  = (const float*)d_in[11];
    const float* ln2b  = (const float*)d_in[12];
    const float* Win   = (const float*)d_in[13];
    const float* bin   = (const float*)d_in[14];
    const float* Wout  = (const float*)d_in[15];
    const float* bout  = (const float*)d_in[16];

    float *mid, *biasqkv;
    bf16 *xh, *xl, *qkvh_, *qkvl_, *acth, *wh;
    cudaGetSymbolAddress((void**)&mid,   g_mid);
    cudaGetSymbolAddress((void**)&biasqkv, g_bias);
    cudaGetSymbolAddress((void**)&xh,    g_xh);
    cudaGetSymbolAddress((void**)&xl,    g_xl);
    cudaGetSymbolAddress((void**)&qkvh_, g_qkvh);
    cudaGetSymbolAddress((void**)&qkvl_, g_qkvl);
    cudaGetSymbolAddress((void**)&acth,  g_acth);
    cudaGetSymbolAddress((void**)&wh,    g_wh);

    // fp16 aliases
    __half* x16h   = (__half*)xh;
    __half* x16l   = (__half*)xl;
    __half* qkv16h = (__half*)qkvh_;
    __half* qkv16l = (__half*)qkvl_;
    __half* a16    = (__half*)acth;
    __half* w16    = (__half*)wh;

    cudaFuncSetAttribute(attn_mma, cudaFuncAttributeMaxDynamicSharedMemorySize,
                         ATTN_SMEM);
    cudaFuncSetAttribute(gemm_f16<EPI_QKV16>,
                         cudaFuncAttributeMaxDynamicSharedMemorySize, GEMM2_SMEM);
    cudaFuncSetAttribute(gemm_f16<EPI_RES32>,
                         cudaFuncAttributeMaxDynamicSharedMemorySize, GEMM2_SMEM);
    cudaFuncSetAttribute(gemm_f16_1t<EPI_GELU16>,
                         cudaFuncAttributeMaxDynamicSharedMemorySize, GEMM1_SMEM);
    cudaFuncSetAttribute(gemm_f16_1t<EPI_RES32>,
                         cudaFuncAttributeMaxDynamicSharedMemorySize, GEMM1_SMEM);

    dim3 tb(32, 8);

    // 1) LN1 -> fp16 split
    ln_split_kernel<<<NTOK, 256>>>(resid, ln1w, ln1b, x16h, x16l);

    // 2) fused QKV (2-term fp16; Q prescaled by 1/8)
    concat_bias<<<12, 256>>>(bQ, bK, bV, biasqkv);
    tsplit16_qkv<<<dim3(DHH/32, DD/32, 48), tb>>>(WQ, WK, WV, w16);
    gemm_f16<EPI_QKV16><<<dim3(3*DD/128, NTOK/128), 256, GEMM2_SMEM>>>(
        x16h, x16l, w16, biasqkv, nullptr, nullptr, qkv16h, qkv16l,
        NTOK, 3*DD, DD);

    // 3) attention (QK 2-term, PV 1-term) -> z fp16 split (into x16h/x16l)
    dim3 ga(SS / 64, BB * HH);
    attn_mma<<<ga, 128, ATTN_SMEM>>>(qkv16h, qkv16l, x16h, x16l);

    // 4) O-projection + residual -> mid (2-term fp16)
    tsplit16_kernel<<<dim3(DD/32, DD/32), tb>>>(WO, w16, DD, DD);
    gemm_f16<EPI_RES32><<<dim3(DD/128, NTOK/128), 256, GEMM2_SMEM>>>(
        x16h, x16l, w16, bO, resid, mid, nullptr, nullptr, NTOK, DD, DD);

    // 5) LN2 -> single fp16
    ln_single_kernel<<<NTOK, 256>>>(mid, ln2w, ln2b, x16h);

    // 6) MLP in + exact GELU -> single fp16 act (1-term)
    tsplit16_kernel<<<dim3(DMM/32, DD/32), tb>>>(Win, w16, DD, DMM);
    gemm_f16_1t<EPI_GELU16><<<dim3(DMM/128, NTOK/128), 256, GEMM1_SMEM>>>(
        x16h, w16, bin, nullptr, nullptr, a16, NTOK, DMM, DD);

    // 7) MLP out + bias + residual -> d_out (1-term)
    tsplit16_kernel<<<dim3(DD/32, DMM/32), tb>>>(Wout, w16, DMM, DD);
    gemm_f16_1t<EPI_RES32><<<dim3(DD/128, NTOK/128), 256, GEMM1_SMEM>>>(
        a16, w16, bout, mid, (float*)d_out, nullptr, NTOK, DD, DMM);
}

// round 17
// speedup vs baseline: 1.9668x; 1.1318x over previous
#include <cuda_runtime.h>
#include <cuda_bf16.h>
#include <cuda_fp16.h>
#include <math.h>
#include <stdint.h>

// Problem constants
#define BB   2
#define SS   2048
#define DD   1024
#define HH   16
#define DHH  64
#define DMM  4096
#define NTOK (BB*SS)          // 4096
#define EPSLN 1e-5f

typedef __nv_bfloat16  bf16;

// ---------------------------------------------------------------------------
// Device scratch (2-byte buffers, fp16 phase)
// ---------------------------------------------------------------------------
__device__ float g_mid[NTOK*DD];
__device__ float g_bias[3*DD];        // concatenated QKV bias
__device__ bf16  g_xh [NTOK*DD];      // activations (single fp16) / z
__device__ bf16  g_qkvh[NTOK*3*DD];   // fused QKV output (hi, fp16)
__device__ bf16  g_qkvl[NTOK*3*DD];   // fused QKV output (lo, fp16)
__device__ bf16  g_acth[NTOK*DMM];    // gelu output (single fp16)
__device__ bf16  g_wh [DD*DMM];       // single transposed weight (fp16)

// ---------------------------------------------------------------------------
// Helpers
// ---------------------------------------------------------------------------
__device__ __forceinline__ void split2h(float x, __half& h, __half& l)
{
    h = __float2half_rn(x);
    l = __float2half_rn(x - __half2float(h));
}

__device__ __forceinline__ uint32_t cvta_s(const void* p)
{
    return (uint32_t)__cvta_generic_to_shared(p);
}

__device__ __forceinline__ void cp16(uint32_t s, const void* g)
{
    asm volatile("cp.async.cg.shared.global [%0], [%1], 16;" :: "r"(s), "l"(g));
}

__device__ __forceinline__ void ldsm4(unsigned r[4], uint32_t a)
{
    asm volatile("ldmatrix.sync.aligned.m8n8.x4.shared.b16 {%0,%1,%2,%3}, [%4];"
                 : "=r"(r[0]), "=r"(r[1]), "=r"(r[2]), "=r"(r[3]) : "r"(a));
}

__device__ __forceinline__ void ldsm4t(unsigned r[4], uint32_t a)
{
    asm volatile("ldmatrix.sync.aligned.m8n8.x4.trans.shared.b16 {%0,%1,%2,%3}, [%4];"
                 : "=r"(r[0]), "=r"(r[1]), "=r"(r[2]), "=r"(r[3]) : "r"(a));
}

// fp16 inputs, fp32 accumulator
__device__ __forceinline__ void mma16816h(float c[4], const unsigned a[4],
                                          const unsigned b[2])
{
    asm volatile(
        "mma.sync.aligned.m16n8k16.row.col.f32.f16.f16.f32 "
        "{%0,%1,%2,%3}, {%4,%5,%6,%7}, {%8,%9}, {%0,%1,%2,%3};"
        : "+f"(c[0]), "+f"(c[1]), "+f"(c[2]), "+f"(c[3])
        : "r"(a[0]), "r"(a[1]), "r"(a[2]), "r"(a[3]), "r"(b[0]), "r"(b[1]));
}

__device__ __forceinline__ float gelu_exact(float x)
{
    return 0.5f * x * (1.0f + erff(x * 0.70710678118654752f));
}

// ---------------------------------------------------------------------------
// LayerNorm -> single fp16. One block per row, 256 threads.
// ---------------------------------------------------------------------------
__global__ __launch_bounds__(256)
void ln_single_kernel(const float* __restrict__ x, const float* __restrict__ w,
                      const float* __restrict__ b, __half* __restrict__ oh)
{
    __shared__ float red[8];
    __shared__ float bcast;
    const int row = blockIdx.x;
    const int tid = threadIdx.x;
    const int lane = tid & 31, warp = tid >> 5;

    float4 v = ((const float4*)(x + (size_t)row * DD))[tid];

    float s = v.x + v.y + v.z + v.w;
    #pragma unroll
    for (int o = 16; o > 0; o >>= 1) s += __shfl_xor_sync(0xffffffffu, s, o);
    if (lane == 0) red[warp] = s;
    __syncthreads();
    if (tid < 8) {
        float t = red[tid];
        #pragma unroll
        for (int o = 4; o > 0; o >>= 1) t += __shfl_xor_sync(0xffu, t, o);
        if (tid == 0) bcast = t;
    }
    __syncthreads();
    const float mean = bcast * (1.0f / DD);
    __syncthreads();

    float dx0 = v.x - mean, dx1 = v.y - mean, dx2 = v.z - mean, dx3 = v.w - mean;
    float sq = dx0*dx0 + dx1*dx1 + dx2*dx2 + dx3*dx3;
    #pragma unroll
    for (int o = 16; o > 0; o >>= 1) sq += __shfl_xor_sync(0xffffffffu, sq, o);
    if (lane == 0) red[warp] = sq;
    __syncthreads();
    if (tid < 8) {
        float t = red[tid];
        #pragma unroll
        for (int o = 4; o > 0; o >>= 1) t += __shfl_xor_sync(0xffu, t, o);
        if (tid == 0) bcast = t;
    }
    __syncthreads();
    const float inv = rsqrtf(bcast * (1.0f / DD) + EPSLN);

    float4 wv = ((const float4*)w)[tid];
    float4 bv = ((const float4*)b)[tid];
    float o0 = dx0 * inv * wv.x + bv.x;
    float o1 = dx1 * inv * wv.y + bv.y;
    float o2 = dx2 * inv * wv.z + bv.z;
    float o3 = dx3 * inv * wv.w + bv.w;

    __half2* H = (__half2*)(oh + (size_t)row * DD + tid * 4);
    H[0] = __halves2half2(__float2half_rn(o0), __float2half_rn(o1));
    H[1] = __halves2half2(__float2half_rn(o2), __float2half_rn(o3));
}

// ---------------------------------------------------------------------------
// Concatenate QKV biases into g_bias[3072]
// ---------------------------------------------------------------------------
__global__ void concat_bias(const float* __restrict__ bq,
                            const float* __restrict__ bk,
                            const float* __restrict__ bv,
                            float* __restrict__ out)
{
    int i = blockIdx.x * blockDim.x + threadIdx.x;
    float v;
    if (i < DD) v = bq[i];
    else if (i < 2*DD) v = bk[i - DD];
    else v = bv[i - 2*DD];
    out[i] = v;
}

// ---------------------------------------------------------------------------
// Transpose + single-fp16 convert: o16[c*R + r] = fp16(in[r][c])
// ---------------------------------------------------------------------------
__global__ __launch_bounds__(256)
void tsplit16_kernel(const float* __restrict__ in, __half* __restrict__ o16,
                     int R, int C)
{
    __shared__ float t[32][33];
    const int tx = threadIdx.x, ty = threadIdx.y;
    const int c0 = blockIdx.x * 32, r0 = blockIdx.y * 32;
    #pragma unroll
    for (int i = 0; i < 4; i++)
        t[ty + 8*i][tx] = in[(size_t)(r0 + ty + 8*i) * C + c0 + tx];
    __syncthreads();
    #pragma unroll
    for (int i = 0; i < 4; i++) {
        int c = c0 + ty + 8*i;
        o16[(size_t)c * R + r0 + tx] = __float2half_rn(t[tx][ty + 8*i]);
    }
}

// ---------------------------------------------------------------------------
// Transpose + single-fp16 for QKV weights
// ---------------------------------------------------------------------------
__global__ __launch_bounds__(256)
void tsplit16_qkv(const float* __restrict__ wq, const float* __restrict__ wk,
                  const float* __restrict__ wv, __half* __restrict__ o16)
{
    __shared__ float t[32][33];
    const int tx = threadIdx.x, ty = threadIdx.y;
    const int c0 = blockIdx.x * 32, r0 = blockIdx.y * 32;
    const int z = blockIdx.z;
    const int which = z >> 4, h = z & 15;
    const float* src = (which == 0 ? wq : (which == 1 ? wk : wv))
                       + (size_t)h * DD * DHH;
    #pragma unroll
    for (int i = 0; i < 4; i++)
        t[ty + 8*i][tx] = src[(size_t)(r0 + ty + 8*i) * DHH + c0 + tx];
    __syncthreads();
    #pragma unroll
    for (int i = 0; i < 4; i++) {
        int c = c0 + ty + 8*i;
        size_t n = (size_t)which * DD + h * DHH + c;
        o16[n * DD + r0 + tx] = __float2half_rn(t[tx][ty + 8*i]);
    }
}

// ---------------------------------------------------------------------------
// 1-term fp16 GEMM: C = A16 @ B16 (f32 acc). All four block GEMMs.
// EPI: 1 = bias+gelu -> fp16      2 = bias+residual -> fp32
//      3 = QKV: bias + Q-scale -> split fp16 hi/lo (exact split of f32)
// ---------------------------------------------------------------------------
#define EPI_GELU16 1
#define EPI_RES32  2
#define EPI_QKV16  3

#define TILE_BYTES 8192             // 128 rows * 64B
#define STG1_BYTES (2*TILE_BYTES)   // A, B = 16KB
#define GEMM1_SMEM (3*STG1_BYTES)   // 49152 B

template <int EPI>
__global__ __launch_bounds__(256, 2)
void gemm_f16_1t(const __half* __restrict__ Am, const __half* __restrict__ Bm,
                 const float* __restrict__ bias, const float* __restrict__ Rm,
                 float* __restrict__ Cf, __half* __restrict__ Oh,
                 __half* __restrict__ Ol, int M, int N, int K)
{
    extern __shared__ bf16 sm[];
    const int tid = threadIdx.x;
    const int bx = blockIdx.x, by = blockIdx.y;
    const int warp = tid >> 5, lane = tid & 31;
    const int wm = warp >> 1, wn = warp & 1;

    const int lrow = tid >> 1;
    const int lhalf = (tid & 1);
    const __half* gA = Am + (size_t)(by * 128 + lrow) * K + lhalf * 16;
    const __half* gB = Bm + (size_t)(bx * 128 + lrow) * K + lhalf * 16;
    const uint32_t sbase = cvta_s(sm);
    const uint32_t lxm = (uint32_t)((lrow & 6) << 3);
    const uint32_t lso0 = lrow * 64 + ((lhalf * 32)      ^ lxm);
    const uint32_t lso1 = lrow * 64 + ((lhalf * 32 + 16) ^ lxm);

    float acc[2][8][4];
    #pragma unroll
    for (int i = 0; i < 2; i++)
        #pragma unroll
        for (int j = 0; j < 8; j++)
            #pragma unroll
            for (int q = 0; q < 4; q++) acc[i][j][q] = 0.0f;

    const int a_r = (lane & 7) + ((lane >> 3) & 1) * 8;
    const int a_c = (lane >> 4) * 8;
    const int b_r = (lane & 7) + (lane >> 4) * 8;
    const int b_c = ((lane >> 3) & 1) * 8;

    uint32_t arow[2], axm[2];
    #pragma unroll
    for (int mf = 0; mf < 2; mf++) {
        int r = wm*32 + mf*16 + a_r;
        arow[mf] = (uint32_t)r * 64;
        axm[mf]  = (uint32_t)((r & 6) << 3);
    }
    uint32_t brow[4], bxm[4];
    #pragma unroll
    for (int p = 0; p < 4; p++) {
        int r = wn*64 + p*16 + b_r;
        brow[p] = (uint32_t)r * 64;
        bxm[p]  = (uint32_t)((r & 6) << 3);
    }
    const uint32_t acb = (uint32_t)(a_c * 2);
    const uint32_t bcb = (uint32_t)(b_c * 2);

    const int T = K / 32;

    auto issue = [&](int s, int kk) {
        uint32_t st = sbase + (uint32_t)s * STG1_BYTES;
        cp16(st + lso0,              gA + kk);
        cp16(st + lso1,              gA + kk + 8);
        cp16(st + TILE_BYTES + lso0, gB + kk);
        cp16(st + TILE_BYTES + lso1, gB + kk + 8);
        asm volatile("cp.async.commit_group;");
    };

    issue(0, 0);
    if (T > 1) issue(1, 32);

    int stage = 0;
    for (int t = 0; t < T; t++) {
        if (t + 2 < T) {
            issue((stage + 2) % 3, (t + 2) * 32);
            asm volatile("cp.async.wait_group 2;");
        } else if (t + 1 < T) {
            asm volatile("cp.async.wait_group 1;");
        } else {
            asm volatile("cp.async.wait_group 0;");
        }
        __syncthreads();

        const uint32_t st = sbase + (uint32_t)stage * STG1_BYTES;
        const uint32_t sA = st;
        const uint32_t sB = st + TILE_BYTES;

        #pragma unroll
        for (int kc = 0; kc < 2; kc++) {
            const uint32_t kb = (uint32_t)(kc * 32);
            unsigned a4[2][4];
            #pragma unroll
            for (int mf = 0; mf < 2; mf++) {
                uint32_t ao = arow[mf] + ((kb + acb) ^ axm[mf]);
                ldsm4(a4[mf], sA + ao);
            }
            #pragma unroll
            for (int p = 0; p < 4; p++) {
                unsigned b4[4];
                uint32_t bo = brow[p] + ((kb + bcb) ^ bxm[p]);
                ldsm4(b4, sB + bo);
                #pragma unroll
                for (int mf = 0; mf < 2; mf++) {
                    mma16816h(acc[mf][2*p],     a4[mf], b4);
                    mma16816h(acc[mf][2*p + 1], a4[mf], b4 + 2);
                }
            }
        }
        __syncthreads();
        stage = (stage + 1) % 3;
    }

    const int er = by * 128 + wm * 32 + (lane >> 2);
    const int ec = bx * 128 + wn * 64 + (lane & 3) * 2;
    #pragma unroll
    for (int mf = 0; mf < 2; mf++) {
        #pragma unroll
        for (int nf = 0; nf < 8; nf++) {
            int c = ec + nf * 8;
            float b0 = bias[c], b1 = bias[c + 1];
            #pragma unroll
            for (int half = 0; half < 2; half++) {
                int r = er + mf * 16 + half * 8;
                float v0 = acc[mf][nf][half * 2 + 0] + b0;
                float v1 = acc[mf][nf][half * 2 + 1] + b1;
                if (EPI == EPI_QKV16) {
                    float sc = (c < DD) ? 0.125f : 1.0f;
                    v0 *= sc; v1 *= sc;
                    __half h0,h1,l0,l1;
                    split2h(v0,h0,l0); split2h(v1,h1,l1);
                    *(__half2*)(Oh + (size_t)r * N + c) = __halves2half2(h0, h1);
                    *(__half2*)(Ol + (size_t)r * N + c) = __halves2half2(l0, l1);
                } else if (EPI == EPI_GELU16) {
                    v0 = gelu_exact(v0); v1 = gelu_exact(v1);
                    *(__half2*)(Oh + (size_t)r * N + c) =
                        __halves2half2(__float2half_rn(v0), __float2half_rn(v1));
                } else {
                    float2 rr = *(const float2*)(Rm + (size_t)r * N + c);
                    v0 += rr.x; v1 += rr.y;
                    float2 o; o.x = v0; o.y = v1;
                    *(float2*)(Cf + (size_t)r * N + c) = o;
                }
            }
        }
    }
}

// ---------------------------------------------------------------------------
// Tensor-core flash attention, fp16:
//   S = (Qh + Ql) @ Kh^T  (2-term, q exact)    O = Ph @ Vh  (1-term)
// Output z as single fp16.
// ---------------------------------------------------------------------------
#define AQS   72
#define ATILE (64*AQS)
#define ATTN_SMEM ((2*ATILE + 2*2*ATILE) * 2)   // Qh,Ql + 2 stages * {Kh,Vh}

__global__ __launch_bounds__(128, 2)
void attn_mma(const __half* __restrict__ qkvh, const __half* __restrict__ qkvl,
              __half* __restrict__ zh)
{
    extern __shared__ bf16 smb[];
    const uint32_t sbase = cvta_s(smb);
    const int tid  = threadIdx.x;
    const int warp = tid >> 5, lane = tid & 31;
    const int qt = blockIdx.x;
    const int bh = blockIdx.y;
    const int h  = bh & 15;
    const int hcol = h * DHH;
    const int tokbase = (bh >> 4) * SS;

    const uint32_t oQh = 0, oQl = ATILE;
    auto stageoff = [](int s) { return (uint32_t)(2*ATILE + s*2*ATILE); };

    const int ldrow = tid >> 1;
    const int ldc0  = (tid & 1) * 32;
    auto ld_tensor = [&](uint32_t selems, const __half* g, int tok0, int coff) {
        const __half* gp = g + (size_t)(tok0 + ldrow) * (3*DD) + coff + ldc0;
        uint32_t sp = sbase + (selems + ldrow * AQS + ldc0) * 2;
        cp16(sp,      gp);
        cp16(sp + 16, gp + 8);
        cp16(sp + 32, gp + 16);
        cp16(sp + 48, gp + 24);
    };
    auto issue_kv = [&](int s, int kt) {
        int tok0 = tokbase + kt * 64;
        uint32_t so = stageoff(s);
        ld_tensor(so,           qkvh, tok0, DD   + hcol);   // Kh
        ld_tensor(so + ATILE,   qkvh, tok0, 2*DD + hcol);   // Vh
        asm volatile("cp.async.commit_group;");
    };

    {
        int tok0 = tokbase + qt * 64;
        ld_tensor(oQh, qkvh, tok0, hcol);
        ld_tensor(oQl, qkvl, tok0, hcol);
        issue_kv(0, 0);
    }

    const int a_r  = (lane & 7) + ((lane >> 3) & 1) * 8;
    const int a_c  = (lane >> 4) * 8;
    const int kb_r = (lane & 7) + (lane >> 4) * 8;
    const int kb_c = ((lane >> 3) & 1) * 8;
    const int vb_r = (lane & 7) + ((lane >> 3) & 1) * 8;
    const int vb_c = (lane >> 4) * 8;

    unsigned qh[4][4], ql[4][4];
    float o[8][4];
    #pragma unroll
    for (int j = 0; j < 8; j++)
        #pragma unroll
        for (int q = 0; q < 4; q++) o[j][q] = 0.0f;
    float m0 = -INFINITY, m1 = -INFINITY, l0 = 0.0f, l1 = 0.0f;

    const int r0 = lane >> 2;
    const int colq = 2 * (lane & 3);

    for (int kt = 0; kt <= qt; kt++) {
        if (kt + 1 <= qt) {
            issue_kv((kt + 1) & 1, kt + 1);
            asm volatile("cp.async.wait_group 1;");
        } else {
            asm volatile("cp.async.wait_group 0;");
        }
        __syncthreads();

        if (kt == 0) {
            #pragma unroll
            for (int kc = 0; kc < 4; kc++) {
                uint32_t ao = ((warp*16 + a_r) * AQS + kc*16 + a_c) * 2;
                ldsm4(qh[kc], sbase + (oQh)*2 + ao);
                ldsm4(ql[kc], sbase + (oQl)*2 + ao);
            }
        }

        const uint32_t so = stageoff(kt & 1);
        const uint32_t sKh = sbase + so * 2;
        const uint32_t sVh = sbase + (so + ATILE) * 2;

        // ---- S = (Qh + Ql) @ Kh^T ----
        float s[8][4];
        #pragma unroll
        for (int j = 0; j < 8; j++)
            #pragma unroll
            for (int q = 0; q < 4; q++) s[j][q] = 0.0f;

        #pragma unroll
        for (int jp = 0; jp < 4; jp++) {
            #pragma unroll
            for (int kc = 0; kc < 4; kc++) {
                unsigned kh4[4];
                uint32_t ko = ((jp*16 + kb_r) * AQS + kc*16 + kb_c) * 2;
                ldsm4(kh4, sKh + ko);
                mma16816h(s[2*jp],   qh[kc], kh4);
                mma16816h(s[2*jp+1], qh[kc], kh4 + 2);
                mma16816h(s[2*jp],   ql[kc], kh4);
                mma16816h(s[2*jp+1], ql[kc], kh4 + 2);
            }
        }

        if (kt == qt) {
            const int rg0 = warp*16 + r0;
            #pragma unroll
            for (int j = 0; j < 8; j++) {
                int cg = j*8 + colq;
                if (cg     > rg0) s[j][0] = -1e30f;
                if (cg + 1 > rg0) s[j][1] = -1e30f;
                if (cg     > rg0 + 8) s[j][2] = -1e30f;
                if (cg + 1 > rg0 + 8) s[j][3] = -1e30f;
            }
        }

        float vmax0 = -INFINITY, vmax1 = -INFINITY;
        #pragma unroll
        for (int j = 0; j < 8; j++) {
            vmax0 = fmaxf(vmax0, fmaxf(s[j][0], s[j][1]));
            vmax1 = fmaxf(vmax1, fmaxf(s[j][2], s[j][3]));
        }
        vmax0 = fmaxf(vmax0, __shfl_xor_sync(0xffffffffu, vmax0, 1));
        vmax0 = fmaxf(vmax0, __shfl_xor_sync(0xffffffffu, vmax0, 2));
        vmax1 = fmaxf(vmax1, __shfl_xor_sync(0xffffffffu, vmax1, 1));
        vmax1 = fmaxf(vmax1, __shfl_xor_sync(0xffffffffu, vmax1, 2));

        float mn0 = fmaxf(m0, vmax0), mn1 = fmaxf(m1, vmax1);
        float f0 = __expf(m0 - mn0), f1 = __expf(m1 - mn1);
        m0 = mn0; m1 = mn1;

        float rs0 = 0.0f, rs1 = 0.0f;
        #pragma unroll
        for (int j = 0; j < 8; j++) {
            s[j][0] = __expf(s[j][0] - mn0);
            s[j][1] = __expf(s[j][1] - mn0);
            s[j][2] = __expf(s[j][2] - mn1);
            s[j][3] = __expf(s[j][3] - mn1);
            rs0 += s[j][0] + s[j][1];
            rs1 += s[j][2] + s[j][3];
        }
        rs0 += __shfl_xor_sync(0xffffffffu, rs0, 1);
        rs0 += __shfl_xor_sync(0xffffffffu, rs0, 2);
        rs1 += __shfl_xor_sync(0xffffffffu, rs1, 1);
        rs1 += __shfl_xor_sync(0xffffffffu, rs1, 2);
        l0 = l0 * f0 + rs0;
        l1 = l1 * f1 + rs1;

        #pragma unroll
        for (int j = 0; j < 8; j++) {
            o[j][0] *= f0; o[j][1] *= f0;
            o[j][2] *= f1; o[j][3] *= f1;
        }

        // ---- repack P (hi only) into fp16 A fragments ----
        unsigned ph[4][4];
        #pragma unroll
        for (int jc = 0; jc < 4; jc++) {
            const int j0 = 2*jc, j1 = 2*jc + 1;
            __half2 t0 = __halves2half2(__float2half_rn(s[j0][0]),
                                        __float2half_rn(s[j0][1]));
            __half2 t1 = __halves2half2(__float2half_rn(s[j0][2]),
                                        __float2half_rn(s[j0][3]));
            __half2 t2 = __halves2half2(__float2half_rn(s[j1][0]),
                                        __float2half_rn(s[j1][1]));
            __half2 t3 = __halves2half2(__float2half_rn(s[j1][2]),
                                        __float2half_rn(s[j1][3]));
            ph[jc][0] = *reinterpret_cast<unsigned*>(&t0);
            ph[jc][1] = *reinterpret_cast<unsigned*>(&t1);
            ph[jc][2] = *reinterpret_cast<unsigned*>(&t2);
            ph[jc][3] = *reinterpret_cast<unsigned*>(&t3);
        }

        // ---- O += Ph @ Vh ----
        #pragma unroll
        for (int jc = 0; jc < 4; jc++) {
            #pragma unroll
            for (int np = 0; np < 4; np++) {
                unsigned vh4[4];
                uint32_t vo = ((jc*16 + vb_r) * AQS + np*16 + vb_c) * 2;
                ldsm4t(vh4, sVh + vo);
                mma16816h(o[2*np],   ph[jc], vh4);
                mma16816h(o[2*np+1], ph[jc], vh4 + 2);
            }
        }
        __syncthreads();
    }

    // ---- finalize: z = O / l -> single fp16 ----
    const float il0 = 1.0f / l0, il1 = 1.0f / l1;
    const int row0 = tokbase + qt*64 + warp*16 + r0;
    #pragma unroll
    for (int j = 0; j < 8; j++) {
        int c = hcol + j*8 + colq;
        *(__half2*)(zh + (size_t)row0 * DD + c) =
            __halves2half2(__float2half_rn(o[j][0] * il0),
                           __float2half_rn(o[j][1] * il0));
        *(__half2*)(zh + (size_t)(row0 + 8) * DD + c) =
            __halves2half2(__float2half_rn(o[j][2] * il1),
                           __float2half_rn(o[j][3] * il1));
    }
}

// ---------------------------------------------------------------------------
// Host launcher
// ---------------------------------------------------------------------------
extern "C" void kernel_launch(void* const* d_in, const int* in_sizes, int n_in,
                              void* d_out, int out_size)
{
    (void)in_sizes; (void)n_in; (void)out_size;
    const float* resid = (const float*)d_in[0];
    const float* ln1w  = (const float*)d_in[1];
    const float* ln1b  = (const float*)d_in[2];
    const float* WQ    = (const float*)d_in[3];
    const float* bQ    = (const float*)d_in[4];
    const float* WK    = (const float*)d_in[5];
    const float* bK    = (const float*)d_in[6];
    const float* WV    = (const float*)d_in[7];
    const float* bV    = (const float*)d_in[8];
    const float* WO    = (const float*)d_in[9];
    const float* bO    = (const float*)d_in[10];
    const float* ln2w  = (const float*)d_in[11];
    const float* ln2b  = (const float*)d_in[12];
    const float* Win   = (const float*)d_in[13];
    const float* bin   = (const float*)d_in[14];
    const float* Wout  = (const float*)d_in[15];
    const float* bout  = (const float*)d_in[16];

    float *mid, *biasqkv;
    bf16 *xh, *qkvh_, *qkvl_, *acth, *wh;
    cudaGetSymbolAddress((void**)&mid,   g_mid);
    cudaGetSymbolAddress((void**)&biasqkv, g_bias);
    cudaGetSymbolAddress((void**)&xh,    g_xh);
    cudaGetSymbolAddress((void**)&qkvh_, g_qkvh);
    cudaGetSymbolAddress((void**)&qkvl_, g_qkvl);
    cudaGetSymbolAddress((void**)&acth,  g_acth);
    cudaGetSymbolAddress((void**)&wh,    g_wh);

    // fp16 aliases
    __half* x16    = (__half*)xh;
    __half* qkv16h = (__half*)qkvh_;
    __half* qkv16l = (__half*)qkvl_;
    __half* a16    = (__half*)acth;
    __half* w16    = (__half*)wh;

    cudaFuncSetAttribute(attn_mma, cudaFuncAttributeMaxDynamicSharedMemorySize,
                         ATTN_SMEM);
    cudaFuncSetAttribute(gemm_f16_1t<EPI_QKV16>,
                         cudaFuncAttributeMaxDynamicSharedMemorySize, GEMM1_SMEM);
    cudaFuncSetAttribute(gemm_f16_1t<EPI_GELU16>,
                         cudaFuncAttributeMaxDynamicSharedMemorySize, GEMM1_SMEM);
    cudaFuncSetAttribute(gemm_f16_1t<EPI_RES32>,
                         cudaFuncAttributeMaxDynamicSharedMemorySize, GEMM1_SMEM);

    dim3 tb(32, 8);

    // 1) LN1 -> single fp16
    ln_single_kernel<<<NTOK, 256>>>(resid, ln1w, ln1b, x16);

    // 2) fused QKV (1-term; epilogue splits f32 result -> q hi/lo exact)
    concat_bias<<<12, 256>>>(bQ, bK, bV, biasqkv);
    tsplit16_qkv<<<dim3(DHH/32, DD/32, 48), tb>>>(WQ, WK, WV, w16);
    gemm_f16_1t<EPI_QKV16><<<dim3(3*DD/128, NTOK/128), 256, GEMM1_SMEM>>>(
        x16, w16, biasqkv, nullptr, nullptr, qkv16h, qkv16l, NTOK, 3*DD, DD);

    // 3) attention (QK 2-term in q, PV 1-term) -> z single fp16 (into x16)
    dim3 ga(SS / 64, BB * HH);
    attn_mma<<<ga, 128, ATTN_SMEM>>>(qkv16h, qkv16l, x16);

    // 4) O-projection + residual -> mid (1-term)
    tsplit16_kernel<<<dim3(DD/32, DD/32), tb>>>(WO, w16, DD, DD);
    gemm_f16_1t<EPI_RES32><<<dim3(DD/128, NTOK/128), 256, GEMM1_SMEM>>>(
        x16, w16, bO, resid, mid, nullptr, nullptr, NTOK, DD, DD);

    // 5) LN2 -> single fp16
    ln_single_kernel<<<NTOK, 256>>>(mid, ln2w, ln2b, x16);

    // 6) MLP in + exact GELU -> single fp16 act (1-term)
    tsplit16_kernel<<<dim3(DMM/32, DD/32), tb>>>(Win, w16, DD, DMM);
    gemm_f16_1t<EPI_GELU16><<<dim3(DMM/128, NTOK/128), 256, GEMM1_SMEM>>>(
        x16, w16, bin, nullptr, nullptr, a16, nullptr, NTOK, DMM, DD);

    // 7) MLP out + bias + residual -> d_out (1-term)
    tsplit16_kernel<<<dim3(DD/32, DMM/32), tb>>>(Wout, w16, DMM, DD);
    gemm_f16_1t<EPI_RES32><<<dim3(DD/128, NTOK/128), 256, GEMM1_SMEM>>>(
        a16, w16, bout, mid, (float*)d_out, nullptr, nullptr, NTOK, DD, DMM);
}